// round 8
// baseline (speedup 1.0000x reference)
#include <cuda_runtime.h>
#include <cuda_bf16.h>
#include <cstdint>

#define NN   50000
#define NE   1600000
#define DIN  2000
#define H1   500
#define H2   128
#define DD   64

// ---------------- scratch (static device globals; no allocation) ----------------
static __device__ unsigned       g_w1p[2 * (DIN / 2) * H1];   // bf16 pair-packed W1
static __device__ unsigned       g_w2p[2 * (H1 / 2) * H2];
static __device__ unsigned       g_wdp[2 * (H2 / 2) * DD];
static __device__ __nv_bfloat16  g_z1h[2 * NN * H1];          // 100 MB
static __device__ __nv_bfloat16  g_z2h[2 * NN * H2];          // 25.6 MB
static __device__ float g_feat[NN * DD];
static __device__ float g_xw[NN * DD];
static __device__ float g_agg[NN * DD];
static __device__ float g_y1[NN * DD];
static __device__ float g_y2[NN * 32];
static __device__ float g_cs[NN];
static __device__ float g_cd[NN];
static __device__ float g_alpha1[2 * H1], g_beta1[2 * H1];
static __device__ float g_alpha2[2 * H2], g_beta2[2 * H2];
static __device__ float g_betad[2 * DD];

// ---------------- helpers ----------------
__device__ __forceinline__ void mma_bf16(float* c, const unsigned* a, const unsigned* b)
{
    asm volatile(
        "mma.sync.aligned.m16n8k16.row.col.f32.bf16.bf16.f32 "
        "{%0,%1,%2,%3}, {%4,%5,%6,%7}, {%8,%9}, {%0,%1,%2,%3};\n"
        : "+f"(c[0]), "+f"(c[1]), "+f"(c[2]), "+f"(c[3])
        : "r"(a[0]), "r"(a[1]), "r"(a[2]), "r"(a[3]), "r"(b[0]), "r"(b[1]));
}

__device__ __forceinline__ void cp_async16(uint32_t dst, const void* src, int sz)
{
    asm volatile("cp.async.cg.shared.global [%0], [%1], 16, %2;"
                 :: "r"(dst), "l"(src), "r"(sz));
}

__device__ __forceinline__ unsigned pack_bf16(float lo, float hi)
{
    __nv_bfloat162 p = __floats2bfloat162_rn(lo, hi);   // lo -> low 16 bits
    return *(unsigned*)&p;
}

// ---------------- prep kernels ----------------
__global__ void prep_kernel(const float* __restrict__ b1, const float* __restrict__ g1,
                            const float* __restrict__ be1, const float* __restrict__ m1,
                            const float* __restrict__ v1,
                            const float* __restrict__ b2, const float* __restrict__ g2,
                            const float* __restrict__ be2, const float* __restrict__ m2,
                            const float* __restrict__ v2,
                            const float* __restrict__ bd)
{
    int t = threadIdx.x;
    for (int i = t; i < 2 * H1; i += blockDim.x) {
        float a = g1[i] * rsqrtf(v1[i] + 1e-5f);
        g_alpha1[i] = a;
        g_beta1[i]  = (b1[i] - m1[i]) * a + be1[i];
    }
    for (int i = t; i < 2 * H2; i += blockDim.x) {
        float a = g2[i] * rsqrtf(v2[i] + 1e-5f);
        g_alpha2[i] = a;
        g_beta2[i]  = (b2[i] - m2[i]) * a + be2[i];
    }
    for (int i = t; i < 2 * DD; i += blockDim.x)
        g_betad[i] = 0.5f * bd[i];
}

// pack W[K][Nc] fp32 -> Wp[K/2][Nc] u32 (bf16 k-pairs)
__global__ void pack_w_kernel(const float* __restrict__ W, unsigned* __restrict__ Wp,
                              int K, int Nc)
{
    int idx = blockIdx.x * blockDim.x + threadIdx.x;
    int K2 = (K + 1) / 2;
    if (idx >= K2 * Nc) return;
    int k2 = idx / Nc;
    int n  = idx - k2 * Nc;
    float lo = W[(size_t)(2 * k2) * Nc + n];
    float hi = (2 * k2 + 1 < K) ? W[(size_t)(2 * k2 + 1) * Nc + n] : 0.f;
    Wp[idx] = pack_bf16(lo, hi);
}

__global__ void zero_kernel(float* __restrict__ p, int n)
{
    int i = blockIdx.x * blockDim.x + threadIdx.x;
    if (i < n) p[i] = 0.0f;
}

__global__ void deg_count_kernel(const int* __restrict__ src, const int* __restrict__ dst)
{
    int i = blockIdx.x * blockDim.x + threadIdx.x;
    if (i < NE) {
        atomicAdd(&g_cs[src[i]], 1.0f);
        atomicAdd(&g_cd[dst[i]], 1.0f);
    }
}

__global__ void deg_finish_kernel()
{
    int i = blockIdx.x * blockDim.x + threadIdx.x;
    if (i < NN) {
        g_cs[i] = rsqrtf(fmaxf(g_cs[i], 1.0f));
        g_cd[i] = rsqrtf(fmaxf(g_cd[i], 1.0f));
    }
}

// ============ BF16 tensor-core GEMM, 128x128 block / 64x64 warp tile, k16 MMA ============
// A: fp32 (packed to bf16 pairs on load) or bf16 row-major. B: pre-packed u32 pairs [K/2][Nc].
#define TBM 128
#define TBN 128
#define TBK 32
#define AP32 36    // As pitch in u32: bank = (4q + k2) mod 32 -> conflict-free
#define BP32 136   // Bs pitch in u32: bank = (8*(lane&3) + q) mod 32 -> conflict-free
#define SMEM_BYTES ((2 * TBM * AP32 + 2 * (TBK / 2) * BP32) * 4)

__global__ __launch_bounds__(128, 2)
void gemm_bf16_kernel(const float* __restrict__ Af, const __nv_bfloat16* __restrict__ Ah,
                      const unsigned* __restrict__ Bp,
                      float* __restrict__ Cf, __nv_bfloat16* __restrict__ Ch,
                      int M, int K, int Nc,
                      const float* __restrict__ colScale, const float* __restrict__ colBias,
                      float scalarAlpha, int accumulate)
{
    extern __shared__ unsigned smem[];
    unsigned* AsBase = smem;                         // [2][TBM*AP32]
    unsigned* BsBase = smem + 2 * TBM * AP32;        // [2][16*BP32]

    const int t    = threadIdx.x;
    const int warp = t >> 5;
    const int lane = t & 31;
    const int bm   = blockIdx.y * TBM;
    const int bn   = blockIdx.x * TBN;
    const int wm   = (warp >> 1) * 64;
    const int wn   = (warp & 1) * 64;

    // A loader: 128 threads, chunk = 8 k-elements (4 pair-words), 4 row passes
    const int aChunk = t & 3;            // 0..3 -> k offset aChunk*8
    const int aRowB  = t >> 2;           // 0..31
    // B loader: cp.async 16B, rows of Bs (k2), 4 passes
    const int bRow  = t >> 5;            // 0..3
    const int bCol4 = (t & 31) * 4;      // 0..124

    const int nT = (K + TBK - 1) / TBK;
    const int K2 = (K + 1) / 2;

    uint4 aReg[4];

    auto ldgA = [&](int k0) {
        const int kk = k0 + aChunk * 8;
#pragma unroll
        for (int i = 0; i < 4; i++) {
            int row = bm + aRowB + i * 32;
            uint4 r = make_uint4(0u, 0u, 0u, 0u);
            if (row < M) {
                if (Ah) {
                    const unsigned short* p = (const unsigned short*)Ah + (size_t)row * K + kk;
                    if (kk + 4 <= K) { uint2 u = *(const uint2*)p; r.x = u.x; r.y = u.y; }
                    if (kk + 8 <= K) { uint2 u = *(const uint2*)(p + 4); r.z = u.x; r.w = u.y; }
                } else {
                    const float* p = Af + (size_t)row * K + kk;
                    if (kk + 4 <= K) {
                        float4 v = *(const float4*)p;
                        r.x = pack_bf16(v.x, v.y); r.y = pack_bf16(v.z, v.w);
                    }
                    if (kk + 8 <= K) {
                        float4 v = *(const float4*)(p + 4);
                        r.z = pack_bf16(v.x, v.y); r.w = pack_bf16(v.z, v.w);
                    }
                }
            }
            aReg[i] = r;
        }
    };
    auto stsA = [&](int buf) {
        unsigned* As = AsBase + buf * (TBM * AP32);
#pragma unroll
        for (int i = 0; i < 4; i++)
            *(uint4*)(As + (aRowB + i * 32) * AP32 + aChunk * 4) = aReg[i];
    };
    auto cpB = [&](int k0, int buf) {
        unsigned* Bs = BsBase + buf * (16 * BP32);
        const int k2base = k0 >> 1;
#pragma unroll
        for (int i = 0; i < 4; i++) {
            int k2 = bRow + i * 4;
            int sz = ((k2base + k2) < K2 && (bn + bCol4) < Nc) ? 16 : 0;   // Nc % 4 == 0
            cp_async16((uint32_t)__cvta_generic_to_shared(Bs + k2 * BP32 + bCol4),
                       Bp + (size_t)(k2base + k2) * Nc + bn + bCol4, sz);
        }
        asm volatile("cp.async.commit_group;");
    };

    float acc[4][8][4];
#pragma unroll
    for (int mi = 0; mi < 4; mi++)
#pragma unroll
        for (int ni = 0; ni < 8; ni++)
#pragma unroll
            for (int j = 0; j < 4; j++) acc[mi][ni][j] = 0.f;

    ldgA(0);
    cpB(0, 0);

    for (int tt = 0; tt < nT; tt++) {
        const int buf = tt & 1;
        stsA(buf);
        asm volatile("cp.async.wait_group 0;");
        __syncthreads();
        if (tt + 1 < nT) {
            ldgA((tt + 1) * TBK);
            cpB((tt + 1) * TBK, buf ^ 1);
        }

        const unsigned* As = AsBase + buf * (TBM * AP32);
        const unsigned* Bs = BsBase + buf * (16 * BP32);

#pragma unroll
        for (int ks = 0; ks < 2; ks++) {          // two k16 steps per 32-k tile
            const int k2o = ks * 8;
            const int kq  = k2o + (lane & 3);
            unsigned bf[8][2];
#pragma unroll
            for (int ni = 0; ni < 8; ni++) {
                int n = wn + ni * 8 + (lane >> 2);
                bf[ni][0] = Bs[kq * BP32 + n];
                bf[ni][1] = Bs[(kq + 4) * BP32 + n];
            }
#pragma unroll
            for (int mi = 0; mi < 4; mi++) {
                int r = wm + mi * 16 + (lane >> 2);
                unsigned af[4];
                af[0] = As[r * AP32 + kq];
                af[1] = As[(r + 8) * AP32 + kq];
                af[2] = As[r * AP32 + kq + 4];
                af[3] = As[(r + 8) * AP32 + kq + 4];
#pragma unroll
                for (int ni = 0; ni < 8; ni++)
                    mma_bf16(acc[mi][ni], af, bf[ni]);
            }
        }
        __syncthreads();
    }

    // ---- fused epilogue (C fragment mapping identical to verified k8 kernels) ----
#pragma unroll
    for (int mi = 0; mi < 4; mi++) {
        int rbase = bm + wm + mi * 16 + (lane >> 2);
#pragma unroll
        for (int half = 0; half < 2; half++) {
            int row = rbase + half * 8;
            if (row >= M) continue;
#pragma unroll
            for (int ni = 0; ni < 8; ni++) {
                int cbase = bn + wn + ni * 8 + 2 * (lane & 3);
                if (cbase >= Nc) continue;       // Nc even -> pair fully valid
                float v[2];
#pragma unroll
                for (int j = 0; j < 2; j++) {
                    int col = cbase + j;
                    float csv = colScale ? colScale[col] : scalarAlpha;
                    float x = acc[mi][ni][half * 2 + j] * csv;
                    if (colBias) x += colBias[col];
                    v[j] = x;
                }
                size_t idx = (size_t)row * Nc + cbase;
                if (Ch) {
                    *(unsigned*)((unsigned short*)Ch + idx) = pack_bf16(v[0], v[1]);
                } else {
                    if (accumulate) { v[0] += Cf[idx]; v[1] += Cf[idx + 1]; }
                    Cf[idx] = v[0];
                    Cf[idx + 1] = v[1];
                }
            }
        }
    }
}

// ---------------- SIMT 64x64 GEMM (small graph layers only) ----------------
__global__ __launch_bounds__(256)
void gemm64_kernel(const float* __restrict__ A, const float* __restrict__ B,
                   float* __restrict__ C, int M, int K, int Nc,
                   const float* __restrict__ colScale, const float* __restrict__ colBias,
                   const float* __restrict__ rowScale, float scalarAlpha,
                   int accumulate, int relu)
{
    __shared__ float As[16][64];
    __shared__ float Bs[16][64];

    const int t  = threadIdx.x;
    const int bm = blockIdx.y * 64;
    const int bn = blockIdx.x * 64;

    const int a_row = t >> 2;
    const int a_col = (t & 3) * 4;
    const int b_row = t >> 4;
    const int b_col = (t & 15) * 4;

    const int tx = t & 15;
    const int ty = t >> 4;

    float acc[4][4];
#pragma unroll
    for (int i = 0; i < 4; i++)
#pragma unroll
        for (int j = 0; j < 4; j++) acc[i][j] = 0.0f;

    for (int k0 = 0; k0 < K; k0 += 16) {
        float4 av = make_float4(0.f, 0.f, 0.f, 0.f);
        int ar = bm + a_row;
        if (ar < M) {
            if (k0 + a_col + 3 < K) {
                av = *(const float4*)(A + (size_t)ar * K + k0 + a_col);
            } else {
                float tmp[4] = {0.f, 0.f, 0.f, 0.f};
#pragma unroll
                for (int i = 0; i < 4; i++) {
                    int kk = k0 + a_col + i;
                    if (kk < K) tmp[i] = A[(size_t)ar * K + kk];
                }
                av = make_float4(tmp[0], tmp[1], tmp[2], tmp[3]);
            }
        }
        As[a_col + 0][a_row] = av.x;
        As[a_col + 1][a_row] = av.y;
        As[a_col + 2][a_row] = av.z;
        As[a_col + 3][a_row] = av.w;

        float4 bv = make_float4(0.f, 0.f, 0.f, 0.f);
        int brr = k0 + b_row;
        int bcc = bn + b_col;
        if (brr < K) {
            if (bcc + 3 < Nc) {
                bv = *(const float4*)(B + (size_t)brr * Nc + bcc);
            } else {
                float tmp[4] = {0.f, 0.f, 0.f, 0.f};
#pragma unroll
                for (int i = 0; i < 4; i++) {
                    int cc = bcc + i;
                    if (cc < Nc) tmp[i] = B[(size_t)brr * Nc + cc];
                }
                bv = make_float4(tmp[0], tmp[1], tmp[2], tmp[3]);
            }
        }
        *(float4*)&Bs[b_row][b_col] = bv;

        __syncthreads();

#pragma unroll
        for (int k = 0; k < 16; k++) {
            float4 a = *(const float4*)&As[k][ty * 4];
            float4 b = *(const float4*)&Bs[k][tx * 4];
            acc[0][0] += a.x * b.x; acc[0][1] += a.x * b.y; acc[0][2] += a.x * b.z; acc[0][3] += a.x * b.w;
            acc[1][0] += a.y * b.x; acc[1][1] += a.y * b.y; acc[1][2] += a.y * b.z; acc[1][3] += a.y * b.w;
            acc[2][0] += a.z * b.x; acc[2][1] += a.z * b.y; acc[2][2] += a.z * b.z; acc[2][3] += a.z * b.w;
            acc[3][0] += a.w * b.x; acc[3][1] += a.w * b.y; acc[3][2] += a.w * b.z; acc[3][3] += a.w * b.w;
        }
        __syncthreads();
    }

#pragma unroll
    for (int i = 0; i < 4; i++) {
        int row = bm + ty * 4 + i;
        if (row >= M) continue;
        float rs = rowScale ? rowScale[row] : 1.0f;
#pragma unroll
        for (int j = 0; j < 4; j++) {
            int col = bn + tx * 4 + j;
            if (col >= Nc) continue;
            float cs = colScale ? colScale[col] : scalarAlpha;
            float v = acc[i][j] * rs * cs;
            if (colBias) v += colBias[col];
            size_t idx = (size_t)row * Nc + col;
            if (accumulate) v += C[idx];
            if (relu) v = fmaxf(v, 0.0f);
            C[idx] = v;
        }
    }
}

// ---------------- edge scatter: agg[dst] += xw[src] (vector reductions) ----------------
__global__ void scatter_kernel(const float* __restrict__ xw, float* __restrict__ agg,
                               const int* __restrict__ src, const int* __restrict__ dst,
                               int dout4)
{
    int idx = blockIdx.x * blockDim.x + threadIdx.x;
    int total = NE * dout4;
    if (idx >= total) return;
    int e = idx / dout4;
    int c = (idx - e * dout4) * 4;
    int dout = dout4 * 4;
    int s = src[e], d = dst[e];
    float4 v = *(const float4*)(xw + (size_t)s * dout + c);
    float* p = agg + (size_t)d * dout + c;
    asm volatile("red.global.add.v4.f32 [%0], {%1, %2, %3, %4};"
                 :: "l"(p), "f"(v.x), "f"(v.y), "f"(v.z), "f"(v.w) : "memory");
}

__global__ void finalize_kernel(const float* __restrict__ agg, float* __restrict__ out,
                                const float* __restrict__ bias, int dout, int relu)
{
    int idx = blockIdx.x * blockDim.x + threadIdx.x;
    if (idx >= NN * dout) return;
    int n = idx / dout;
    int c = idx - n * dout;
    float v = agg[idx] * g_cd[n] + bias[c];
    if (relu) v = fmaxf(v, 0.0f);
    out[idx] = v;
}

// ---------------- launch ----------------
static inline dim3 tc_grid(int M, int Nc)
{
    return dim3((Nc + TBN - 1) / TBN, (M + TBM - 1) / TBM);
}
static inline dim3 gemm_grid(int M, int Nc)
{
    return dim3((Nc + 63) / 64, (M + 63) / 64);
}

extern "C" void kernel_launch(void* const* d_in, const int* in_sizes, int n_in,
                              void* d_out, int out_size)
{
    const float* h   = (const float*)d_in[0];
    const int*   src = (const int*)  d_in[1];
    const int*   dst = (const int*)  d_in[2];
    const float* W1  = (const float*)d_in[3];
    const float* b1  = (const float*)d_in[4];
    const float* g1  = (const float*)d_in[5];
    const float* be1 = (const float*)d_in[6];
    const float* m1  = (const float*)d_in[7];
    const float* v1  = (const float*)d_in[8];
    const float* W2  = (const float*)d_in[9];
    const float* b2  = (const float*)d_in[10];
    const float* g2  = (const float*)d_in[11];
    const float* be2 = (const float*)d_in[12];
    const float* m2  = (const float*)d_in[13];
    const float* v2  = (const float*)d_in[14];
    const float* Wd  = (const float*)d_in[15];
    const float* bd  = (const float*)d_in[16];
    const float* Wg0 = (const float*)d_in[17];
    const float* bg0 = (const float*)d_in[18];
    const float* Wg1 = (const float*)d_in[19];
    const float* bg1 = (const float*)d_in[20];
    const float* Wg2 = (const float*)d_in[21];
    const float* bg2 = (const float*)d_in[22];
    float* out = (float*)d_out;

    unsigned *w1p, *w2p, *wdp;
    __nv_bfloat16 *z1h, *z2h;
    float *feat, *xw, *agg, *y1, *y2, *cs, *cd;
    float *alpha1, *beta1, *alpha2, *beta2, *betad;
    cudaGetSymbolAddress((void**)&w1p, g_w1p);
    cudaGetSymbolAddress((void**)&w2p, g_w2p);
    cudaGetSymbolAddress((void**)&wdp, g_wdp);
    cudaGetSymbolAddress((void**)&z1h, g_z1h);
    cudaGetSymbolAddress((void**)&z2h, g_z2h);
    cudaGetSymbolAddress((void**)&feat, g_feat);
    cudaGetSymbolAddress((void**)&xw, g_xw);
    cudaGetSymbolAddress((void**)&agg, g_agg);
    cudaGetSymbolAddress((void**)&y1, g_y1);
    cudaGetSymbolAddress((void**)&y2, g_y2);
    cudaGetSymbolAddress((void**)&cs, g_cs);
    cudaGetSymbolAddress((void**)&cd, g_cd);
    cudaGetSymbolAddress((void**)&alpha1, g_alpha1);
    cudaGetSymbolAddress((void**)&beta1, g_beta1);
    cudaGetSymbolAddress((void**)&alpha2, g_alpha2);
    cudaGetSymbolAddress((void**)&beta2, g_beta2);
    cudaGetSymbolAddress((void**)&betad, g_betad);

    cudaFuncSetAttribute(gemm_bf16_kernel, cudaFuncAttributeMaxDynamicSharedMemorySize, SMEM_BYTES);

    prep_kernel<<<1, 512>>>(b1, g1, be1, m1, v1, b2, g2, be2, m2, v2, bd);

    // pack weights to bf16 k-pairs
    for (int m = 0; m < 2; m++) {
        int n = (DIN / 2) * H1;
        pack_w_kernel<<<(n + 255) / 256, 256>>>(W1 + (size_t)m * DIN * H1, w1p + (size_t)m * n, DIN, H1);
        n = (H1 / 2) * H2;
        pack_w_kernel<<<(n + 255) / 256, 256>>>(W2 + (size_t)m * H1 * H2, w2p + (size_t)m * n, H1, H2);
        n = (H2 / 2) * DD;
        pack_w_kernel<<<(n + 255) / 256, 256>>>(Wd + (size_t)m * H2 * DD, wdp + (size_t)m * n, H2, DD);
    }

    zero_kernel<<<(NN + 255) / 256, 256>>>(cs, NN);
    zero_kernel<<<(NN + 255) / 256, 256>>>(cd, NN);
    deg_count_kernel<<<(NE + 255) / 256, 256>>>(src, dst);
    deg_finish_kernel<<<(NN + 255) / 256, 256>>>();

    // encoder layer 1: z1h[m] = bf16( BN1(h[m] @ W1[m] + b1[m]) )
    for (int m = 0; m < 2; m++) {
        gemm_bf16_kernel<<<tc_grid(NN, H1), 128, SMEM_BYTES>>>(
            h + (size_t)m * NN * DIN, nullptr, w1p + (size_t)m * (DIN / 2) * H1,
            nullptr, z1h + (size_t)m * NN * H1, NN, DIN, H1,
            alpha1 + m * H1, beta1 + m * H1, 1.0f, 0);
    }

    // encoder layer 2: z2h[m] = bf16( BN2(z1h[m] @ W2[m] + b2[m]) )
    for (int m = 0; m < 2; m++) {
        gemm_bf16_kernel<<<tc_grid(NN, H2), 128, SMEM_BYTES>>>(
            nullptr, z1h + (size_t)m * NN * H1, w2p + (size_t)m * (H1 / 2) * H2,
            nullptr, z2h + (size_t)m * NN * H2, NN, H1, H2,
            alpha2 + m * H2, beta2 + m * H2, 1.0f, 0);
    }

    // decoder + modality mean: feat = 0.5*sum_m (z2h[m] @ Wd[m] + bd[m])  (fp32 out)
    gemm_bf16_kernel<<<tc_grid(NN, DD), 128, SMEM_BYTES>>>(
        nullptr, z2h, wdp,
        feat, nullptr, NN, H2, DD,
        nullptr, betad, 0.5f, 0);
    gemm_bf16_kernel<<<tc_grid(NN, DD), 128, SMEM_BYTES>>>(
        nullptr, z2h + (size_t)NN * H2, wdp + (size_t)(H2 / 2) * DD,
        feat, nullptr, NN, H2, DD,
        nullptr, betad + DD, 0.5f, 1);

    // ---- GraphConv 1: 64 -> 64, relu ----
    zero_kernel<<<(NN * DD + 255) / 256, 256>>>(agg, NN * DD);
    gemm64_kernel<<<gemm_grid(NN, DD), 256>>>(
        feat, Wg0, xw, NN, DD, DD, nullptr, nullptr, cs, 1.0f, 0, 0);
    scatter_kernel<<<(NE * 16 + 255) / 256, 256>>>(xw, agg, src, dst, 16);
    finalize_kernel<<<(NN * DD + 255) / 256, 256>>>(agg, y1, bg0, DD, 1);

    // ---- GraphConv 2: 64 -> 32, relu ----
    zero_kernel<<<(NN * 32 + 255) / 256, 256>>>(agg, NN * 32);
    gemm64_kernel<<<gemm_grid(NN, 32), 256>>>(
        y1, Wg1, xw, NN, DD, 32, nullptr, nullptr, cs, 1.0f, 0, 0);
    scatter_kernel<<<(NE * 8 + 255) / 256, 256>>>(xw, agg, src, dst, 8);
    finalize_kernel<<<(NN * 32 + 255) / 256, 256>>>(agg, y2, bg1, 32, 1);

    // ---- GraphConv 3: 32 -> 4, no relu, write output ----
    zero_kernel<<<(NN * 4 + 255) / 256, 256>>>(agg, NN * 4);
    gemm64_kernel<<<gemm_grid(NN, 4), 256>>>(
        y2, Wg2, xw, NN, 32, 4, nullptr, nullptr, cs, 1.0f, 0, 0);
    scatter_kernel<<<(NE * 1 + 255) / 256, 256>>>(xw, agg, src, dst, 1);
    finalize_kernel<<<(NN * 4 + 255) / 256, 256>>>(agg, out, bg2, 4, 0);
}

// round 10
// speedup vs baseline: 2.4010x; 2.4010x over previous
#include <cuda_runtime.h>
#include <cstdint>

#define NN   50000
#define NE   1600000
#define DIN  2000
#define H1   500
#define H2   128
#define DD   64
#define KTOT (2 * DIN)   // 4000

// ---------------- scratch (static device globals; no allocation) ----------------
static __device__ float g_w2s[2 * H1 * H2];     // alpha1-scaled W2
static __device__ float g_wds[2 * H2 * DD];     // alpha2-scaled Wd
static __device__ float g_t1[2 * DIN * H2];     // W1 @ W2s
static __device__ float g_beff[KTOT * DD];      // [4000][64] effective weights (tf32-rounded)
static __device__ float g_biasEff[DD];
static __device__ float g_feat[NN * DD];
static __device__ float g_xw[NN * DD];
static __device__ float g_agg[NN * DD];
static __device__ float g_y1[NN * DD];
static __device__ float g_y2[NN * 32];
static __device__ float g_cs[NN];
static __device__ float g_cd[NN];
static __device__ float g_alpha1[2 * H1], g_beta1[2 * H1];
static __device__ float g_alpha2[2 * H2], g_beta2[2 * H2];

// ---------------- tf32 helpers ----------------
__device__ __forceinline__ unsigned f2tf(float x)
{
    unsigned r;
    asm("cvt.rna.tf32.f32 %0, %1;" : "=r"(r) : "f"(x));
    return r;
}
__device__ __forceinline__ float f2tff(float x) { return __uint_as_float(f2tf(x)); }

__device__ __forceinline__ void mma_tf32(float* c, const unsigned* a, const unsigned* b)
{
    asm volatile(
        "mma.sync.aligned.m16n8k8.row.col.f32.tf32.tf32.f32 "
        "{%0,%1,%2,%3}, {%4,%5,%6,%7}, {%8,%9}, {%0,%1,%2,%3};\n"
        : "+f"(c[0]), "+f"(c[1]), "+f"(c[2]), "+f"(c[3])
        : "r"(a[0]), "r"(a[1]), "r"(a[2]), "r"(a[3]), "r"(b[0]), "r"(b[1]));
}

__device__ __forceinline__ void cp_async16(uint32_t dst, const void* src)
{
    asm volatile("cp.async.cg.shared.global [%0], [%1], 16;" :: "r"(dst), "l"(src));
}

// ---------------- prep: BN fold vectors ----------------
__global__ void prep_kernel(const float* __restrict__ b1, const float* __restrict__ g1,
                            const float* __restrict__ be1, const float* __restrict__ m1,
                            const float* __restrict__ v1,
                            const float* __restrict__ b2, const float* __restrict__ g2,
                            const float* __restrict__ be2, const float* __restrict__ m2,
                            const float* __restrict__ v2)
{
    int t = threadIdx.x;
    for (int i = t; i < 2 * H1; i += blockDim.x) {
        float a = g1[i] * rsqrtf(v1[i] + 1e-5f);
        g_alpha1[i] = a;
        g_beta1[i]  = (b1[i] - m1[i]) * a + be1[i];
    }
    for (int i = t; i < 2 * H2; i += blockDim.x) {
        float a = g2[i] * rsqrtf(v2[i] + 1e-5f);
        g_alpha2[i] = a;
        g_beta2[i]  = (b2[i] - m2[i]) * a + be2[i];
    }
}

// out[k][n] = scale[k] * W[k][n]
__global__ void scale_rows_kernel(const float* __restrict__ W, const float* __restrict__ scale,
                                  float* __restrict__ out, int K, int N)
{
    int idx = blockIdx.x * blockDim.x + threadIdx.x;
    if (idx >= K * N) return;
    int k = idx / N;
    out[idx] = scale[k] * W[idx];
}

// biasEff[d] = sum_m 0.5*( ((beta1_m @ W2_m + b2_m)*alpha2_m + beta2_m) @ Wd_m + bd_m )
__global__ void bias_chain_kernel(const float* __restrict__ W2, const float* __restrict__ b2,
                                  const float* __restrict__ Wd, const float* __restrict__ bd)
{
    __shared__ float v[2][H2];
    int t = threadIdx.x;   // 128 threads
    for (int m = 0; m < 2; m++) {
        float u = b2[m * H2 + t];
        for (int k = 0; k < H1; k++)
            u += g_beta1[m * H1 + k] * W2[(size_t)m * H1 * H2 + k * H2 + t];
        v[m][t] = u * g_alpha2[m * H2 + t] + g_beta2[m * H2 + t];
    }
    __syncthreads();
    if (t < DD) {
        float s = 0.f;
        for (int m = 0; m < 2; m++) {
            float tmp = bd[m * DD + t];
            for (int n = 0; n < H2; n++)
                tmp += v[m][n] * Wd[(size_t)m * H2 * DD + n * DD + t];
            s += 0.5f * tmp;
        }
        g_biasEff[t] = s;
    }
}

__global__ void round_tf32_kernel(float* __restrict__ p, int n4)
{
    int i = blockIdx.x * blockDim.x + threadIdx.x;
    if (i < n4) {
        float4 v = ((float4*)p)[i];
        v.x = f2tff(v.x); v.y = f2tff(v.y); v.z = f2tff(v.z); v.w = f2tff(v.w);
        ((float4*)p)[i] = v;
    }
}

__global__ void zero_kernel(float* __restrict__ p, int n)
{
    int i = blockIdx.x * blockDim.x + threadIdx.x;
    if (i < n) p[i] = 0.0f;
}

__global__ void deg_count_kernel(const int* __restrict__ src, const int* __restrict__ dst)
{
    int i = blockIdx.x * blockDim.x + threadIdx.x;
    if (i < NE) {
        atomicAdd(&g_cs[src[i]], 1.0f);
        atomicAdd(&g_cd[dst[i]], 1.0f);
    }
}

__global__ void deg_finish_kernel()
{
    int i = blockIdx.x * blockDim.x + threadIdx.x;
    if (i < NN) {
        g_cs[i] = rsqrtf(fmaxf(g_cs[i], 1.0f));
        g_cd[i] = rsqrtf(fmaxf(g_cd[i], 1.0f));
    }
}

// ============ main encoder GEMM: feat = [h0|h1] @ Beff + biasEff (tf32 TC) ============
// 128x64 block tile, 4 warps (64x32 warp tile), double-buffered cp.async B, LDG+cvt A.
#define TBM 128
#define TBN 64
#define TBK 32
#define APW 36    // bank = (4r + c) mod 32 -> conflict-free (verified R7 layout)
#define BPW 72    // bank = (8k + n) mod 32 -> conflict-free (verified R6 layout)
#define ENC_SMEM ((2 * TBM * APW + 2 * TBK * BPW) * 4)

__global__ __launch_bounds__(128, 2)
void enc_gemm_kernel(const float* __restrict__ h0, const float* __restrict__ h1,
                     const float* __restrict__ Beff, const float* __restrict__ bias,
                     float* __restrict__ C)
{
    extern __shared__ float smem[];
    float* AsBase = smem;                        // [2][TBM*APW]
    float* BsBase = smem + 2 * TBM * APW;        // [2][TBK*BPW]

    const int t    = threadIdx.x;
    const int warp = t >> 5;
    const int lane = t & 31;
    const int bm   = blockIdx.x * TBM;
    const int wm   = (warp >> 1) * 64;
    const int wn   = (warp & 1) * 32;

    const int aRow = t >> 3;             // 0..15, 8 passes of 16 rows
    const int aCol = (t & 7) * 4;        // 0..28
    const int bRow = t >> 4;             // 0..7, 4 passes of 8 k-rows
    const int bCol = (t & 15) * 4;       // 0..60

    const int nT = KTOT / TBK;           // 125

    float4 aReg[8];

    auto ldgA = [&](int k0) {
        const int kk = k0 + aCol;
        const float* base = (kk < DIN) ? (h0 + kk) : (h1 + kk - DIN);
#pragma unroll
        for (int i = 0; i < 8; i++) {
            int row = bm + aRow + i * 16;
            float4 v = make_float4(0.f, 0.f, 0.f, 0.f);
            if (row < NN)
                v = *(const float4*)(base + (size_t)row * DIN);
            v.x = f2tff(v.x); v.y = f2tff(v.y); v.z = f2tff(v.z); v.w = f2tff(v.w);
            aReg[i] = v;
        }
    };
    auto stsA = [&](int buf) {
        float* As = AsBase + buf * (TBM * APW);
#pragma unroll
        for (int i = 0; i < 8; i++)
            *(float4*)(As + (aRow + i * 16) * APW + aCol) = aReg[i];
    };
    auto cpB = [&](int k0, int buf) {
        float* Bs = BsBase + buf * (TBK * BPW);
#pragma unroll
        for (int i = 0; i < 4; i++) {
            int k = bRow + i * 8;
            cp_async16((uint32_t)__cvta_generic_to_shared(Bs + k * BPW + bCol),
                       Beff + (size_t)(k0 + k) * DD + bCol);
        }
        asm volatile("cp.async.commit_group;");
    };

    float acc[4][4][4];
#pragma unroll
    for (int mi = 0; mi < 4; mi++)
#pragma unroll
        for (int ni = 0; ni < 4; ni++)
#pragma unroll
            for (int j = 0; j < 4; j++) acc[mi][ni][j] = 0.f;

    ldgA(0);
    cpB(0, 0);

    for (int tt = 0; tt < nT; tt++) {
        const int buf = tt & 1;
        stsA(buf);
        asm volatile("cp.async.wait_group 0;");
        __syncthreads();
        if (tt + 1 < nT) {
            ldgA((tt + 1) * TBK);
            cpB((tt + 1) * TBK, buf ^ 1);
        }

        const float* As = AsBase + buf * (TBM * APW);
        const float* Bs = BsBase + buf * (TBK * BPW);

#pragma unroll
        for (int ks = 0; ks < 4; ks++) {
            const int c = ks * 8 + (lane & 3);
            unsigned bf[4][2];
#pragma unroll
            for (int ni = 0; ni < 4; ni++) {
                int n = wn + ni * 8 + (lane >> 2);
                bf[ni][0] = __float_as_uint(Bs[c * BPW + n]);
                bf[ni][1] = __float_as_uint(Bs[(c + 4) * BPW + n]);
            }
#pragma unroll
            for (int mi = 0; mi < 4; mi++) {
                int r = wm + mi * 16 + (lane >> 2);
                unsigned af[4];
                af[0] = __float_as_uint(As[r * APW + c]);
                af[1] = __float_as_uint(As[(r + 8) * APW + c]);
                af[2] = __float_as_uint(As[r * APW + c + 4]);
                af[3] = __float_as_uint(As[(r + 8) * APW + c + 4]);
#pragma unroll
                for (int ni = 0; ni < 4; ni++)
                    mma_tf32(acc[mi][ni], af, bf[ni]);
            }
        }
        __syncthreads();
    }

    // epilogue: feat = acc + biasEff
#pragma unroll
    for (int mi = 0; mi < 4; mi++) {
        int rbase = bm + wm + mi * 16 + (lane >> 2);
#pragma unroll
        for (int half = 0; half < 2; half++) {
            int row = rbase + half * 8;
            if (row >= NN) continue;
#pragma unroll
            for (int ni = 0; ni < 4; ni++) {
                int cbase = wn + ni * 8 + 2 * (lane & 3);
#pragma unroll
                for (int j = 0; j < 2; j++) {
                    int col = cbase + j;
                    C[(size_t)row * DD + col] = acc[mi][ni][half * 2 + j] + bias[col];
                }
            }
        }
    }
}

// ---------------- SIMT 64x64 GEMM (fold + graph layers) ----------------
__global__ __launch_bounds__(256)
void gemm64_kernel(const float* __restrict__ A, const float* __restrict__ B,
                   float* __restrict__ C, int M, int K, int Nc,
                   const float* __restrict__ rowScale, float scalarAlpha)
{
    __shared__ float As[16][64];
    __shared__ float Bs[16][64];

    const int t  = threadIdx.x;
    const int bm = blockIdx.y * 64;
    const int bn = blockIdx.x * 64;

    const int a_row = t >> 2;
    const int a_col = (t & 3) * 4;
    const int b_row = t >> 4;
    const int b_col = (t & 15) * 4;

    const int tx = t & 15;
    const int ty = t >> 4;

    float acc[4][4];
#pragma unroll
    for (int i = 0; i < 4; i++)
#pragma unroll
        for (int j = 0; j < 4; j++) acc[i][j] = 0.0f;

    for (int k0 = 0; k0 < K; k0 += 16) {
        float4 av = make_float4(0.f, 0.f, 0.f, 0.f);
        int ar = bm + a_row;
        if (ar < M) {
            if (k0 + a_col + 3 < K) {
                av = *(const float4*)(A + (size_t)ar * K + k0 + a_col);
            } else {
                float tmp[4] = {0.f, 0.f, 0.f, 0.f};
#pragma unroll
                for (int i = 0; i < 4; i++) {
                    int kk = k0 + a_col + i;
                    if (kk < K) tmp[i] = A[(size_t)ar * K + kk];
                }
                av = make_float4(tmp[0], tmp[1], tmp[2], tmp[3]);
            }
        }
        As[a_col + 0][a_row] = av.x;
        As[a_col + 1][a_row] = av.y;
        As[a_col + 2][a_row] = av.z;
        As[a_col + 3][a_row] = av.w;

        float4 bv = make_float4(0.f, 0.f, 0.f, 0.f);
        int brr = k0 + b_row;
        int bcc = bn + b_col;
        if (brr < K) {
            if (bcc + 3 < Nc) {
                bv = *(const float4*)(B + (size_t)brr * Nc + bcc);
            } else {
                float tmp[4] = {0.f, 0.f, 0.f, 0.f};
#pragma unroll
                for (int i = 0; i < 4; i++) {
                    int cc = bcc + i;
                    if (cc < Nc) tmp[i] = B[(size_t)brr * Nc + cc];
                }
                bv = make_float4(tmp[0], tmp[1], tmp[2], tmp[3]);
            }
        }
        *(float4*)&Bs[b_row][b_col] = bv;

        __syncthreads();

#pragma unroll
        for (int k = 0; k < 16; k++) {
            float4 a = *(const float4*)&As[k][ty * 4];
            float4 b = *(const float4*)&Bs[k][tx * 4];
            acc[0][0] += a.x * b.x; acc[0][1] += a.x * b.y; acc[0][2] += a.x * b.z; acc[0][3] += a.x * b.w;
            acc[1][0] += a.y * b.x; acc[1][1] += a.y * b.y; acc[1][2] += a.y * b.z; acc[1][3] += a.y * b.w;
            acc[2][0] += a.z * b.x; acc[2][1] += a.z * b.y; acc[2][2] += a.z * b.z; acc[2][3] += a.z * b.w;
            acc[3][0] += a.w * b.x; acc[3][1] += a.w * b.y; acc[3][2] += a.w * b.z; acc[3][3] += a.w * b.w;
        }
        __syncthreads();
    }

#pragma unroll
    for (int i = 0; i < 4; i++) {
        int row = bm + ty * 4 + i;
        if (row >= M) continue;
        float rs = rowScale ? rowScale[row] : scalarAlpha;
#pragma unroll
        for (int j = 0; j < 4; j++) {
            int col = bn + tx * 4 + j;
            if (col >= Nc) continue;
            C[(size_t)row * Nc + col] = acc[i][j] * rs;
        }
    }
}

// ---------------- edge scatter: agg[dst] += xw[src] (vector reductions) ----------------
__global__ void scatter_kernel(const float* __restrict__ xw, float* __restrict__ agg,
                               const int* __restrict__ src, const int* __restrict__ dst,
                               int dout4)
{
    int idx = blockIdx.x * blockDim.x + threadIdx.x;
    int total = NE * dout4;
    if (idx >= total) return;
    int e = idx / dout4;
    int c = (idx - e * dout4) * 4;
    int dout = dout4 * 4;
    int s = src[e], d = dst[e];
    float4 v = *(const float4*)(xw + (size_t)s * dout + c);
    float* p = agg + (size_t)d * dout + c;
    asm volatile("red.global.add.v4.f32 [%0], {%1, %2, %3, %4};"
                 :: "l"(p), "f"(v.x), "f"(v.y), "f"(v.z), "f"(v.w) : "memory");
}

__global__ void finalize_kernel(const float* __restrict__ agg, float* __restrict__ out,
                                const float* __restrict__ bias, int dout, int relu)
{
    int idx = blockIdx.x * blockDim.x + threadIdx.x;
    if (idx >= NN * dout) return;
    int n = idx / dout;
    int c = idx - n * dout;
    float v = agg[idx] * g_cd[n] + bias[c];
    if (relu) v = fmaxf(v, 0.0f);
    out[idx] = v;
}

// ---------------- launch ----------------
static inline dim3 gemm_grid(int M, int Nc)
{
    return dim3((Nc + 63) / 64, (M + 63) / 64);
}

extern "C" void kernel_launch(void* const* d_in, const int* in_sizes, int n_in,
                              void* d_out, int out_size)
{
    const float* h   = (const float*)d_in[0];
    const int*   src = (const int*)  d_in[1];
    const int*   dst = (const int*)  d_in[2];
    const float* W1  = (const float*)d_in[3];
    const float* b1  = (const float*)d_in[4];
    const float* g1  = (const float*)d_in[5];
    const float* be1 = (const float*)d_in[6];
    const float* m1  = (const float*)d_in[7];
    const float* v1  = (const float*)d_in[8];
    const float* W2  = (const float*)d_in[9];
    const float* b2  = (const float*)d_in[10];
    const float* g2  = (const float*)d_in[11];
    const float* be2 = (const float*)d_in[12];
    const float* m2  = (const float*)d_in[13];
    const float* v2  = (const float*)d_in[14];
    const float* Wd  = (const float*)d_in[15];
    const float* bd  = (const float*)d_in[16];
    const float* Wg0 = (const float*)d_in[17];
    const float* bg0 = (const float*)d_in[18];
    const float* Wg1 = (const float*)d_in[19];
    const float* bg1 = (const float*)d_in[20];
    const float* Wg2 = (const float*)d_in[21];
    const float* bg2 = (const float*)d_in[22];
    float* out = (float*)d_out;

    float *w2s, *wds, *t1, *beff, *biasEff;
    float *feat, *xw, *agg, *y1, *y2, *cs, *cd, *alpha1, *alpha2;
    cudaGetSymbolAddress((void**)&w2s, g_w2s);
    cudaGetSymbolAddress((void**)&wds, g_wds);
    cudaGetSymbolAddress((void**)&t1, g_t1);
    cudaGetSymbolAddress((void**)&beff, g_beff);
    cudaGetSymbolAddress((void**)&biasEff, g_biasEff);
    cudaGetSymbolAddress((void**)&feat, g_feat);
    cudaGetSymbolAddress((void**)&xw, g_xw);
    cudaGetSymbolAddress((void**)&agg, g_agg);
    cudaGetSymbolAddress((void**)&y1, g_y1);
    cudaGetSymbolAddress((void**)&y2, g_y2);
    cudaGetSymbolAddress((void**)&cs, g_cs);
    cudaGetSymbolAddress((void**)&cd, g_cd);
    cudaGetSymbolAddress((void**)&alpha1, g_alpha1);
    cudaGetSymbolAddress((void**)&alpha2, g_alpha2);

    cudaFuncSetAttribute(enc_gemm_kernel, cudaFuncAttributeMaxDynamicSharedMemorySize, ENC_SMEM);

    // --- fold the linear encoder into Beff [4000][64] + biasEff [64] ---
    prep_kernel<<<1, 512>>>(b1, g1, be1, m1, v1, b2, g2, be2, m2, v2);
    {
        int n = 2 * H1 * H2;
        scale_rows_kernel<<<(n + 255) / 256, 256>>>(W2, alpha1, w2s, 2 * H1, H2);  // per-m rows via flat index
        n = 2 * H2 * DD;
        scale_rows_kernel<<<(n + 255) / 256, 256>>>(Wd, alpha2, wds, 2 * H2, DD);
    }
    for (int m = 0; m < 2; m++) {
        // T1_m = W1_m @ (diag(a1) W2_m)   [2000 x 128]
        gemm64_kernel<<<gemm_grid(DIN, H2), 256>>>(
            W1 + (size_t)m * DIN * H1, w2s + (size_t)m * H1 * H2,
            t1 + (size_t)m * DIN * H2, DIN, H1, H2, nullptr, 1.0f);
        // Beff_m = 0.5 * T1_m @ (diag(a2) Wd_m)   [2000 x 64]
        gemm64_kernel<<<gemm_grid(DIN, DD), 256>>>(
            t1 + (size_t)m * DIN * H2, wds + (size_t)m * H2 * DD,
            beff + (size_t)m * DIN * DD, DIN, H2, DD, nullptr, 0.5f);
    }
    round_tf32_kernel<<<(KTOT * DD / 4 + 255) / 256, 256>>>(beff, KTOT * DD / 4);
    bias_chain_kernel<<<1, 128>>>(W2, b2, Wd, bd);

    // --- degrees ---
    zero_kernel<<<(NN + 255) / 256, 256>>>(cs, NN);
    zero_kernel<<<(NN + 255) / 256, 256>>>(cd, NN);
    deg_count_kernel<<<(NE + 255) / 256, 256>>>(src, dst);
    deg_finish_kernel<<<(NN + 255) / 256, 256>>>();

    // --- collapsed encoder: feat = h0 @ Beff0 + h1 @ Beff1 + biasEff ---
    enc_gemm_kernel<<<(NN + TBM - 1) / TBM, 128, ENC_SMEM>>>(
        h, h + (size_t)NN * DIN, beff, biasEff, feat);

    // ---- GraphConv 1: 64 -> 64, relu ----
    zero_kernel<<<(NN * DD + 255) / 256, 256>>>(agg, NN * DD);
    gemm64_kernel<<<gemm_grid(NN, DD), 256>>>(feat, Wg0, xw, NN, DD, DD, cs, 1.0f);
    scatter_kernel<<<(NE * 16 + 255) / 256, 256>>>(xw, agg, src, dst, 16);
    finalize_kernel<<<(NN * DD + 255) / 256, 256>>>(agg, y1, bg0, DD, 1);

    // ---- GraphConv 2: 64 -> 32, relu ----
    zero_kernel<<<(NN * 32 + 255) / 256, 256>>>(agg, NN * 32);
    gemm64_kernel<<<gemm_grid(NN, 32), 256>>>(y1, Wg1, xw, NN, DD, 32, cs, 1.0f);
    scatter_kernel<<<(NE * 8 + 255) / 256, 256>>>(xw, agg, src, dst, 8);
    finalize_kernel<<<(NN * 32 + 255) / 256, 256>>>(agg, y2, bg1, 32, 1);

    // ---- GraphConv 3: 32 -> 4, no relu, write output ----
    zero_kernel<<<(NN * 4 + 255) / 256, 256>>>(agg, NN * 4);
    gemm64_kernel<<<gemm_grid(NN, 4), 256>>>(y2, Wg2, xw, NN, 32, 4, cs, 1.0f);
    scatter_kernel<<<(NE * 1 + 255) / 256, 256>>>(xw, agg, src, dst, 1);
    finalize_kernel<<<(NN * 4 + 255) / 256, 256>>>(agg, out, bg2, 4, 0);
}

// round 11
// speedup vs baseline: 3.6596x; 1.5242x over previous
#include <cuda_runtime.h>
#include <cstdint>

#define NN   50000
#define NE   1600000
#define DIN  2000
#define H1   500
#define H2   128
#define DD   64
#define KTOT (2 * DIN)   // 4000

// ---------------- scratch (static device globals; no allocation) ----------------
static __device__ float g_w2s[2 * H1 * H2];     // alpha1-scaled W2
static __device__ float g_wds[2 * H2 * DD];     // alpha2-scaled Wd
static __device__ float g_t2[2 * H1 * DD];      // W2s @ Wds
static __device__ float g_beff[KTOT * DD];      // [4000][64] effective weights (tf32-rounded)
static __device__ float g_biasEff[DD];
static __device__ float g_feat[NN * DD];
static __device__ float g_xw[NN * DD];
static __device__ float g_y1[NN * DD];
static __device__ float g_y2[NN * 32];
static __device__ float g_cs[NN];
static __device__ float g_cd[NN];
static __device__ int   g_indeg[NN];
static __device__ int   g_offs[NN + 1];
static __device__ int   g_cursor[NN];
static __device__ int   g_ein[NE];              // edge src ids grouped by dst
static __device__ float g_alpha1[2 * H1], g_beta1[2 * H1];
static __device__ float g_alpha2[2 * H2], g_beta2[2 * H2];

// ---------------- tf32 helpers ----------------
__device__ __forceinline__ unsigned f2tf(float x)
{
    unsigned r;
    asm("cvt.rna.tf32.f32 %0, %1;" : "=r"(r) : "f"(x));
    return r;
}
__device__ __forceinline__ float f2tff(float x) { return __uint_as_float(f2tf(x)); }

__device__ __forceinline__ void mma_tf32(float* c, const unsigned* a, const unsigned* b)
{
    asm volatile(
        "mma.sync.aligned.m16n8k8.row.col.f32.tf32.tf32.f32 "
        "{%0,%1,%2,%3}, {%4,%5,%6,%7}, {%8,%9}, {%0,%1,%2,%3};\n"
        : "+f"(c[0]), "+f"(c[1]), "+f"(c[2]), "+f"(c[3])
        : "r"(a[0]), "r"(a[1]), "r"(a[2]), "r"(a[3]), "r"(b[0]), "r"(b[1]));
}

__device__ __forceinline__ void cp_async16(uint32_t dst, const void* src)
{
    asm volatile("cp.async.cg.shared.global [%0], [%1], 16;" :: "r"(dst), "l"(src));
}

// ---------------- prep: BN fold vectors ----------------
__global__ void prep_kernel(const float* __restrict__ b1, const float* __restrict__ g1,
                            const float* __restrict__ be1, const float* __restrict__ m1,
                            const float* __restrict__ v1,
                            const float* __restrict__ b2, const float* __restrict__ g2,
                            const float* __restrict__ be2, const float* __restrict__ m2,
                            const float* __restrict__ v2)
{
    int t = threadIdx.x;
    for (int i = t; i < 2 * H1; i += blockDim.x) {
        float a = g1[i] * rsqrtf(v1[i] + 1e-5f);
        g_alpha1[i] = a;
        g_beta1[i]  = (b1[i] - m1[i]) * a + be1[i];
    }
    for (int i = t; i < 2 * H2; i += blockDim.x) {
        float a = g2[i] * rsqrtf(v2[i] + 1e-5f);
        g_alpha2[i] = a;
        g_beta2[i]  = (b2[i] - m2[i]) * a + be2[i];
    }
}

// out[k][n] = scale[k] * W[k][n]  (flat over batch*K rows)
__global__ void scale_rows_kernel(const float* __restrict__ W, const float* __restrict__ scale,
                                  float* __restrict__ out, int K, int N)
{
    int idx = blockIdx.x * blockDim.x + threadIdx.x;
    if (idx >= K * N) return;
    int k = idx / N;
    out[idx] = scale[k] * W[idx];
}

// biasEff[d] = sum_m 0.5*( ((beta1_m @ W2_m + b2_m)*alpha2_m + beta2_m) @ Wd_m + bd_m )
__global__ void bias_chain_kernel(const float* __restrict__ W2, const float* __restrict__ b2,
                                  const float* __restrict__ Wd, const float* __restrict__ bd)
{
    __shared__ float v[2][H2];
    int t = threadIdx.x;   // 128 threads
    for (int m = 0; m < 2; m++) {
        float u = b2[m * H2 + t];
        for (int k = 0; k < H1; k++)
            u += g_beta1[m * H1 + k] * W2[(size_t)m * H1 * H2 + k * H2 + t];
        v[m][t] = u * g_alpha2[m * H2 + t] + g_beta2[m * H2 + t];
    }
    __syncthreads();
    if (t < DD) {
        float s = 0.f;
        for (int m = 0; m < 2; m++) {
            float tmp = bd[m * DD + t];
            for (int n = 0; n < H2; n++)
                tmp += v[m][n] * Wd[(size_t)m * H2 * DD + n * DD + t];
            s += 0.5f * tmp;
        }
        g_biasEff[t] = s;
    }
}

__global__ void round_tf32_kernel(float* __restrict__ p, int n4)
{
    int i = blockIdx.x * blockDim.x + threadIdx.x;
    if (i < n4) {
        float4 v = ((float4*)p)[i];
        v.x = f2tff(v.x); v.y = f2tff(v.y); v.z = f2tff(v.z); v.w = f2tff(v.w);
        ((float4*)p)[i] = v;
    }
}

__global__ void zero_f_kernel(float* __restrict__ p, int n)
{
    int i = blockIdx.x * blockDim.x + threadIdx.x;
    if (i < n) p[i] = 0.0f;
}

__global__ void zero_i_kernel(int* __restrict__ p, int n)
{
    int i = blockIdx.x * blockDim.x + threadIdx.x;
    if (i < n) p[i] = 0;
}

// ---------------- degrees + CSR build ----------------
__global__ void deg_count_kernel(const int* __restrict__ src, const int* __restrict__ dst)
{
    int i = blockIdx.x * blockDim.x + threadIdx.x;
    if (i < NE) {
        atomicAdd(&g_cs[src[i]], 1.0f);
        atomicAdd(&g_indeg[dst[i]], 1);
    }
}

__global__ void deg_finish_kernel()
{
    int i = blockIdx.x * blockDim.x + threadIdx.x;
    if (i < NN) {
        g_cs[i] = rsqrtf(fmaxf(g_cs[i], 1.0f));
        g_cd[i] = rsqrtf(fmaxf((float)g_indeg[i], 1.0f));
    }
}

// single-block exclusive scan of indeg -> offs (NN+1 entries)
__global__ void scan_offsets_kernel()
{
    __shared__ int sh[1024];
    __shared__ int carry;
    int t = threadIdx.x;
    if (t == 0) carry = 0;
    __syncthreads();
    for (int base = 0; base < NN; base += 1024) {
        int v = (base + t < NN) ? g_indeg[base + t] : 0;
        sh[t] = v;
        __syncthreads();
#pragma unroll
        for (int off = 1; off < 1024; off <<= 1) {
            int x = (t >= off) ? sh[t - off] : 0;
            __syncthreads();
            sh[t] += x;
            __syncthreads();
        }
        if (base + t < NN) g_offs[base + t] = carry + sh[t] - v;
        __syncthreads();
        if (t == 0) carry += sh[1023];
        __syncthreads();
    }
    if (t == 0) g_offs[NN] = carry;
}

__global__ void bin_edges_kernel(const int* __restrict__ src, const int* __restrict__ dst)
{
    int e = blockIdx.x * blockDim.x + threadIdx.x;
    if (e < NE) {
        int d = dst[e];
        int p = g_offs[d] + atomicAdd(&g_cursor[d], 1);
        g_ein[p] = src[e];
    }
}

// ============ main encoder GEMM: feat = [h0|h1] @ Beff + biasEff (tf32 TC) ============
#define TBM 128
#define TBN 64
#define TBK 32
#define APW 36
#define BPW 72
#define ENC_SMEM ((2 * TBM * APW + 2 * TBK * BPW) * 4)

__global__ __launch_bounds__(128, 2)
void enc_gemm_kernel(const float* __restrict__ h0, const float* __restrict__ h1,
                     const float* __restrict__ Beff, const float* __restrict__ bias,
                     float* __restrict__ C)
{
    extern __shared__ float smem[];
    float* AsBase = smem;
    float* BsBase = smem + 2 * TBM * APW;

    const int t    = threadIdx.x;
    const int warp = t >> 5;
    const int lane = t & 31;
    const int bm   = blockIdx.x * TBM;
    const int wm   = (warp >> 1) * 64;
    const int wn   = (warp & 1) * 32;

    const int aRow = t >> 3;
    const int aCol = (t & 7) * 4;
    const int bRow = t >> 4;
    const int bCol = (t & 15) * 4;

    const int nT = KTOT / TBK;

    float4 aReg[8];

    auto ldgA = [&](int k0) {
        const int kk = k0 + aCol;
        const float* base = (kk < DIN) ? (h0 + kk) : (h1 + kk - DIN);
#pragma unroll
        for (int i = 0; i < 8; i++) {
            int row = bm + aRow + i * 16;
            float4 v = make_float4(0.f, 0.f, 0.f, 0.f);
            if (row < NN)
                v = *(const float4*)(base + (size_t)row * DIN);
            v.x = f2tff(v.x); v.y = f2tff(v.y); v.z = f2tff(v.z); v.w = f2tff(v.w);
            aReg[i] = v;
        }
    };
    auto stsA = [&](int buf) {
        float* As = AsBase + buf * (TBM * APW);
#pragma unroll
        for (int i = 0; i < 8; i++)
            *(float4*)(As + (aRow + i * 16) * APW + aCol) = aReg[i];
    };
    auto cpB = [&](int k0, int buf) {
        float* Bs = BsBase + buf * (TBK * BPW);
#pragma unroll
        for (int i = 0; i < 4; i++) {
            int k = bRow + i * 8;
            cp_async16((uint32_t)__cvta_generic_to_shared(Bs + k * BPW + bCol),
                       Beff + (size_t)(k0 + k) * DD + bCol);
        }
        asm volatile("cp.async.commit_group;");
    };

    float acc[4][4][4];
#pragma unroll
    for (int mi = 0; mi < 4; mi++)
#pragma unroll
        for (int ni = 0; ni < 4; ni++)
#pragma unroll
            for (int j = 0; j < 4; j++) acc[mi][ni][j] = 0.f;

    ldgA(0);
    cpB(0, 0);

    for (int tt = 0; tt < nT; tt++) {
        const int buf = tt & 1;
        stsA(buf);
        asm volatile("cp.async.wait_group 0;");
        __syncthreads();
        if (tt + 1 < nT) {
            ldgA((tt + 1) * TBK);
            cpB((tt + 1) * TBK, buf ^ 1);
        }

        const float* As = AsBase + buf * (TBM * APW);
        const float* Bs = BsBase + buf * (TBK * BPW);

#pragma unroll
        for (int ks = 0; ks < 4; ks++) {
            const int c = ks * 8 + (lane & 3);
            unsigned bf[4][2];
#pragma unroll
            for (int ni = 0; ni < 4; ni++) {
                int n = wn + ni * 8 + (lane >> 2);
                bf[ni][0] = __float_as_uint(Bs[c * BPW + n]);
                bf[ni][1] = __float_as_uint(Bs[(c + 4) * BPW + n]);
            }
#pragma unroll
            for (int mi = 0; mi < 4; mi++) {
                int r = wm + mi * 16 + (lane >> 2);
                unsigned af[4];
                af[0] = __float_as_uint(As[r * APW + c]);
                af[1] = __float_as_uint(As[(r + 8) * APW + c]);
                af[2] = __float_as_uint(As[r * APW + c + 4]);
                af[3] = __float_as_uint(As[(r + 8) * APW + c + 4]);
#pragma unroll
                for (int ni = 0; ni < 4; ni++)
                    mma_tf32(acc[mi][ni], af, bf[ni]);
            }
        }
        __syncthreads();
    }

#pragma unroll
    for (int mi = 0; mi < 4; mi++) {
        int rbase = bm + wm + mi * 16 + (lane >> 2);
#pragma unroll
        for (int half = 0; half < 2; half++) {
            int row = rbase + half * 8;
            if (row >= NN) continue;
#pragma unroll
            for (int ni = 0; ni < 4; ni++) {
                int cbase = wn + ni * 8 + 2 * (lane & 3);
#pragma unroll
                for (int j = 0; j < 2; j++) {
                    int col = cbase + j;
                    C[(size_t)row * DD + col] = acc[mi][ni][half * 2 + j] + bias[col];
                }
            }
        }
    }
}

// ---------------- SIMT 64x64 GEMM with batch z (fold + graph layers) ----------------
__global__ __launch_bounds__(256)
void gemm64_kernel(const float* __restrict__ A, const float* __restrict__ B,
                   float* __restrict__ C, int M, int K, int Nc,
                   const float* __restrict__ rowScale, float scalarAlpha,
                   size_t aBStride, size_t bBStride, size_t cBStride)
{
    __shared__ float As[16][64];
    __shared__ float Bs[16][64];

    const float* Az = A + blockIdx.z * aBStride;
    const float* Bz = B + blockIdx.z * bBStride;
    float*       Cz = C + blockIdx.z * cBStride;

    const int t  = threadIdx.x;
    const int bm = blockIdx.y * 64;
    const int bn = blockIdx.x * 64;

    const int a_row = t >> 2;
    const int a_col = (t & 3) * 4;
    const int b_row = t >> 4;
    const int b_col = (t & 15) * 4;

    const int tx = t & 15;
    const int ty = t >> 4;

    float acc[4][4];
#pragma unroll
    for (int i = 0; i < 4; i++)
#pragma unroll
        for (int j = 0; j < 4; j++) acc[i][j] = 0.0f;

    for (int k0 = 0; k0 < K; k0 += 16) {
        float4 av = make_float4(0.f, 0.f, 0.f, 0.f);
        int ar = bm + a_row;
        if (ar < M) {
            if (k0 + a_col + 3 < K) {
                av = *(const float4*)(Az + (size_t)ar * K + k0 + a_col);
            } else {
                float tmp[4] = {0.f, 0.f, 0.f, 0.f};
#pragma unroll
                for (int i = 0; i < 4; i++) {
                    int kk = k0 + a_col + i;
                    if (kk < K) tmp[i] = Az[(size_t)ar * K + kk];
                }
                av = make_float4(tmp[0], tmp[1], tmp[2], tmp[3]);
            }
        }
        As[a_col + 0][a_row] = av.x;
        As[a_col + 1][a_row] = av.y;
        As[a_col + 2][a_row] = av.z;
        As[a_col + 3][a_row] = av.w;

        float4 bv = make_float4(0.f, 0.f, 0.f, 0.f);
        int brr = k0 + b_row;
        int bcc = bn + b_col;
        if (brr < K) {
            if (bcc + 3 < Nc) {
                bv = *(const float4*)(Bz + (size_t)brr * Nc + bcc);
            } else {
                float tmp[4] = {0.f, 0.f, 0.f, 0.f};
#pragma unroll
                for (int i = 0; i < 4; i++) {
                    int cc = bcc + i;
                    if (cc < Nc) tmp[i] = Bz[(size_t)brr * Nc + cc];
                }
                bv = make_float4(tmp[0], tmp[1], tmp[2], tmp[3]);
            }
        }
        *(float4*)&Bs[b_row][b_col] = bv;

        __syncthreads();

#pragma unroll
        for (int k = 0; k < 16; k++) {
            float4 a = *(const float4*)&As[k][ty * 4];
            float4 b = *(const float4*)&Bs[k][tx * 4];
            acc[0][0] += a.x * b.x; acc[0][1] += a.x * b.y; acc[0][2] += a.x * b.z; acc[0][3] += a.x * b.w;
            acc[1][0] += a.y * b.x; acc[1][1] += a.y * b.y; acc[1][2] += a.y * b.z; acc[1][3] += a.y * b.w;
            acc[2][0] += a.z * b.x; acc[2][1] += a.z * b.y; acc[2][2] += a.z * b.z; acc[2][3] += a.z * b.w;
            acc[3][0] += a.w * b.x; acc[3][1] += a.w * b.y; acc[3][2] += a.w * b.z; acc[3][3] += a.w * b.w;
        }
        __syncthreads();
    }

#pragma unroll
    for (int i = 0; i < 4; i++) {
        int row = bm + ty * 4 + i;
        if (row >= M) continue;
        float rs = rowScale ? rowScale[row] : scalarAlpha;
#pragma unroll
        for (int j = 0; j < 4; j++) {
            int col = bn + tx * 4 + j;
            if (col >= Nc) continue;
            Cz[(size_t)row * Nc + col] = acc[i][j] * rs;
        }
    }
}

// ---------------- CSR gather-aggregate, fused cd*agg + bias (+relu) ----------------
// dout=64: warp per node, float2 per lane
__global__ void gather64_kernel(const float* __restrict__ xw, float* __restrict__ out,
                                const float* __restrict__ bias)
{
    int node = blockIdx.x * (blockDim.x >> 5) + (threadIdx.x >> 5);
    if (node >= NN) return;
    int lane = threadIdx.x & 31;
    int beg = g_offs[node], end = g_offs[node + 1];
    float ax = 0.f, ay = 0.f;
    for (int e = beg; e < end; e++) {
        int s = g_ein[e];
        float2 v = *(const float2*)(xw + (size_t)s * 64 + lane * 2);
        ax += v.x; ay += v.y;
    }
    float cdv = g_cd[node];
    float o0 = fmaxf(ax * cdv + bias[lane * 2], 0.f);
    float o1 = fmaxf(ay * cdv + bias[lane * 2 + 1], 0.f);
    *(float2*)(out + (size_t)node * 64 + lane * 2) = make_float2(o0, o1);
}

// dout=32: warp per node, 1 float per lane
__global__ void gather32_kernel(const float* __restrict__ xw, float* __restrict__ out,
                                const float* __restrict__ bias)
{
    int node = blockIdx.x * (blockDim.x >> 5) + (threadIdx.x >> 5);
    if (node >= NN) return;
    int lane = threadIdx.x & 31;
    int beg = g_offs[node], end = g_offs[node + 1];
    float a = 0.f;
    for (int e = beg; e < end; e++)
        a += xw[(size_t)g_ein[e] * 32 + lane];
    out[(size_t)node * 32 + lane] = fmaxf(a * g_cd[node] + bias[lane], 0.f);
}

// dout=4: thread per node, float4
__global__ void gather4_kernel(const float* __restrict__ xw, float* __restrict__ out,
                               const float* __restrict__ bias)
{
    int node = blockIdx.x * blockDim.x + threadIdx.x;
    if (node >= NN) return;
    int beg = g_offs[node], end = g_offs[node + 1];
    float4 a = make_float4(0.f, 0.f, 0.f, 0.f);
    for (int e = beg; e < end; e++) {
        float4 v = *(const float4*)(xw + (size_t)g_ein[e] * 4);
        a.x += v.x; a.y += v.y; a.z += v.z; a.w += v.w;
    }
    float cdv = g_cd[node];
    a.x = a.x * cdv + bias[0];
    a.y = a.y * cdv + bias[1];
    a.z = a.z * cdv + bias[2];
    a.w = a.w * cdv + bias[3];
    *(float4*)(out + (size_t)node * 4) = a;
}

// ---------------- launch ----------------
static inline dim3 gemm_grid(int M, int Nc, int z)
{
    return dim3((Nc + 63) / 64, (M + 63) / 64, z);
}

extern "C" void kernel_launch(void* const* d_in, const int* in_sizes, int n_in,
                              void* d_out, int out_size)
{
    const float* h   = (const float*)d_in[0];
    const int*   src = (const int*)  d_in[1];
    const int*   dst = (const int*)  d_in[2];
    const float* W1  = (const float*)d_in[3];
    const float* b1  = (const float*)d_in[4];
    const float* g1  = (const float*)d_in[5];
    const float* be1 = (const float*)d_in[6];
    const float* m1  = (const float*)d_in[7];
    const float* v1  = (const float*)d_in[8];
    const float* W2  = (const float*)d_in[9];
    const float* b2  = (const float*)d_in[10];
    const float* g2  = (const float*)d_in[11];
    const float* be2 = (const float*)d_in[12];
    const float* m2  = (const float*)d_in[13];
    const float* v2  = (const float*)d_in[14];
    const float* Wd  = (const float*)d_in[15];
    const float* bd  = (const float*)d_in[16];
    const float* Wg0 = (const float*)d_in[17];
    const float* bg0 = (const float*)d_in[18];
    const float* Wg1 = (const float*)d_in[19];
    const float* bg1 = (const float*)d_in[20];
    const float* Wg2 = (const float*)d_in[21];
    const float* bg2 = (const float*)d_in[22];
    float* out = (float*)d_out;

    float *w2s, *wds, *t2, *beff, *biasEff;
    float *feat, *xw, *y1, *y2, *cs, *cd, *alpha1, *alpha2;
    int *indeg, *cursor;
    cudaGetSymbolAddress((void**)&w2s, g_w2s);
    cudaGetSymbolAddress((void**)&wds, g_wds);
    cudaGetSymbolAddress((void**)&t2, g_t2);
    cudaGetSymbolAddress((void**)&beff, g_beff);
    cudaGetSymbolAddress((void**)&biasEff, g_biasEff);
    cudaGetSymbolAddress((void**)&feat, g_feat);
    cudaGetSymbolAddress((void**)&xw, g_xw);
    cudaGetSymbolAddress((void**)&y1, g_y1);
    cudaGetSymbolAddress((void**)&y2, g_y2);
    cudaGetSymbolAddress((void**)&cs, g_cs);
    cudaGetSymbolAddress((void**)&cd, g_cd);
    cudaGetSymbolAddress((void**)&alpha1, g_alpha1);
    cudaGetSymbolAddress((void**)&alpha2, g_alpha2);
    cudaGetSymbolAddress((void**)&indeg, g_indeg);
    cudaGetSymbolAddress((void**)&cursor, g_cursor);

    cudaFuncSetAttribute(enc_gemm_kernel, cudaFuncAttributeMaxDynamicSharedMemorySize, ENC_SMEM);

    // --- fold the linear encoder into Beff [4000][64] + biasEff [64] ---
    prep_kernel<<<1, 512>>>(b1, g1, be1, m1, v1, b2, g2, be2, m2, v2);
    {
        int n = 2 * H1 * H2;
        scale_rows_kernel<<<(n + 255) / 256, 256>>>(W2, alpha1, w2s, 2 * H1, H2);
        n = 2 * H2 * DD;
        scale_rows_kernel<<<(n + 255) / 256, 256>>>(Wd, alpha2, wds, 2 * H2, DD);
    }
    // t2_m = (a1 W2_m) @ (a2 Wd_m)   [500 x 64] x2 batched
    gemm64_kernel<<<gemm_grid(H1, DD, 2), 256>>>(
        w2s, wds, t2, H1, H2, DD, nullptr, 1.0f,
        (size_t)H1 * H2, (size_t)H2 * DD, (size_t)H1 * DD);
    // Beff_m = 0.5 * W1_m @ t2_m   [2000 x 64] x2 batched
    gemm64_kernel<<<gemm_grid(DIN, DD, 2), 256>>>(
        W1, t2, beff, DIN, H1, DD, nullptr, 0.5f,
        (size_t)DIN * H1, (size_t)H1 * DD, (size_t)DIN * DD);
    round_tf32_kernel<<<(KTOT * DD / 4 + 255) / 256, 256>>>(beff, KTOT * DD / 4);
    bias_chain_kernel<<<1, 128>>>(W2, b2, Wd, bd);

    // --- degrees + CSR ---
    zero_f_kernel<<<(NN + 255) / 256, 256>>>(cs, NN);
    zero_i_kernel<<<(NN + 255) / 256, 256>>>(indeg, NN);
    zero_i_kernel<<<(NN + 255) / 256, 256>>>(cursor, NN);
    deg_count_kernel<<<(NE + 255) / 256, 256>>>(src, dst);
    deg_finish_kernel<<<(NN + 255) / 256, 256>>>();
    scan_offsets_kernel<<<1, 1024>>>();
    bin_edges_kernel<<<(NE + 255) / 256, 256>>>(src, dst);

    // --- collapsed encoder: feat = h0 @ Beff0 + h1 @ Beff1 + biasEff ---
    enc_gemm_kernel<<<(NN + TBM - 1) / TBM, 128, ENC_SMEM>>>(
        h, h + (size_t)NN * DIN, beff, biasEff, feat);

    // ---- GraphConv 1: 64 -> 64, relu ----
    gemm64_kernel<<<gemm_grid(NN, DD, 1), 256>>>(feat, Wg0, xw, NN, DD, DD, cs, 1.0f, 0, 0, 0);
    gather64_kernel<<<(NN * 32 + 255) / 256, 256>>>(xw, y1, bg0);

    // ---- GraphConv 2: 64 -> 32, relu ----
    gemm64_kernel<<<gemm_grid(NN, 32, 1), 256>>>(y1, Wg1, xw, NN, DD, 32, cs, 1.0f, 0, 0, 0);
    gather32_kernel<<<(NN * 32 + 255) / 256, 256>>>(xw, y2, bg1);

    // ---- GraphConv 3: 32 -> 4, no relu, write output ----
    gemm64_kernel<<<gemm_grid(NN, 4, 1), 256>>>(y2, Wg2, xw, NN, 32, 4, cs, 1.0f, 0, 0, 0);
    gather4_kernel<<<(NN + 255) / 256, 256>>>(xw, out, bg2);
}

// round 12
// speedup vs baseline: 4.3063x; 1.1767x over previous
#include <cuda_runtime.h>
#include <cstdint>

#define NN   50000
#define NE   1600000
#define DIN  2000
#define H1   500
#define H2   128
#define DD   64
#define KTOT (2 * DIN)   // 4000

// ---------------- scratch (static device globals; no allocation) ----------------
static __device__ float g_w2s[2 * H1 * H2];     // alpha1-scaled W2
static __device__ float g_wds[2 * H2 * DD];     // alpha2-scaled Wd
static __device__ float g_t2[2 * H1 * DD];      // W2s @ Wds
static __device__ float g_beff[KTOT * DD];      // [4000][64] effective weights (tf32-rounded)
static __device__ float g_biasEff[DD];
static __device__ float g_feat[NN * DD];
static __device__ float g_xw[NN * DD];
static __device__ float g_y1[NN * DD];
static __device__ float g_y2[NN * 32];
static __device__ float g_cs[NN];
static __device__ float g_cd[NN];
static __device__ int   g_indeg[NN];
static __device__ int   g_offs[NN + 1];
static __device__ int   g_cursor[NN];
static __device__ int   g_ein[NE];              // edge src ids grouped by dst
static __device__ float g_alpha1[2 * H1], g_beta1[2 * H1];
static __device__ float g_alpha2[2 * H2], g_beta2[2 * H2];

// ---------------- tf32 helpers ----------------
__device__ __forceinline__ unsigned f2tf(float x)
{
    unsigned r;
    asm("cvt.rna.tf32.f32 %0, %1;" : "=r"(r) : "f"(x));
    return r;
}
__device__ __forceinline__ float f2tff(float x) { return __uint_as_float(f2tf(x)); }

__device__ __forceinline__ void mma_tf32(float* c, const unsigned* a, const unsigned* b)
{
    asm volatile(
        "mma.sync.aligned.m16n8k8.row.col.f32.tf32.tf32.f32 "
        "{%0,%1,%2,%3}, {%4,%5,%6,%7}, {%8,%9}, {%0,%1,%2,%3};\n"
        : "+f"(c[0]), "+f"(c[1]), "+f"(c[2]), "+f"(c[3])
        : "r"(a[0]), "r"(a[1]), "r"(a[2]), "r"(a[3]), "r"(b[0]), "r"(b[1]));
}

__device__ __forceinline__ void cp_async16z(uint32_t dst, const void* src, int sz)
{
    asm volatile("cp.async.cg.shared.global [%0], [%1], 16, %2;"
                 :: "r"(dst), "l"(src), "r"(sz));
}

// ---------------- prep: BN fold vectors ----------------
__global__ void prep_kernel(const float* __restrict__ b1, const float* __restrict__ g1,
                            const float* __restrict__ be1, const float* __restrict__ m1,
                            const float* __restrict__ v1,
                            const float* __restrict__ b2, const float* __restrict__ g2,
                            const float* __restrict__ be2, const float* __restrict__ m2,
                            const float* __restrict__ v2)
{
    int t = threadIdx.x;
    for (int i = t; i < 2 * H1; i += blockDim.x) {
        float a = g1[i] * rsqrtf(v1[i] + 1e-5f);
        g_alpha1[i] = a;
        g_beta1[i]  = (b1[i] - m1[i]) * a + be1[i];
    }
    for (int i = t; i < 2 * H2; i += blockDim.x) {
        float a = g2[i] * rsqrtf(v2[i] + 1e-5f);
        g_alpha2[i] = a;
        g_beta2[i]  = (b2[i] - m2[i]) * a + be2[i];
    }
}

__global__ void scale_rows_kernel(const float* __restrict__ W, const float* __restrict__ scale,
                                  float* __restrict__ out, int K, int N)
{
    int idx = blockIdx.x * blockDim.x + threadIdx.x;
    if (idx >= K * N) return;
    int k = idx / N;
    out[idx] = scale[k] * W[idx];
}

__global__ void bias_chain_kernel(const float* __restrict__ W2, const float* __restrict__ b2,
                                  const float* __restrict__ Wd, const float* __restrict__ bd)
{
    __shared__ float v[2][H2];
    int t = threadIdx.x;   // 128 threads
    for (int m = 0; m < 2; m++) {
        float u = b2[m * H2 + t];
        for (int k = 0; k < H1; k++)
            u += g_beta1[m * H1 + k] * W2[(size_t)m * H1 * H2 + k * H2 + t];
        v[m][t] = u * g_alpha2[m * H2 + t] + g_beta2[m * H2 + t];
    }
    __syncthreads();
    if (t < DD) {
        float s = 0.f;
        for (int m = 0; m < 2; m++) {
            float tmp = bd[m * DD + t];
            for (int n = 0; n < H2; n++)
                tmp += v[m][n] * Wd[(size_t)m * H2 * DD + n * DD + t];
            s += 0.5f * tmp;
        }
        g_biasEff[t] = s;
    }
}

__global__ void round_tf32_kernel(float* __restrict__ p, int n4)
{
    int i = blockIdx.x * blockDim.x + threadIdx.x;
    if (i < n4) {
        float4 v = ((float4*)p)[i];
        v.x = f2tff(v.x); v.y = f2tff(v.y); v.z = f2tff(v.z); v.w = f2tff(v.w);
        ((float4*)p)[i] = v;
    }
}

// feat[n][c] = biasEff[c]  (float4 granularity)
__global__ void init_feat_kernel(float* __restrict__ feat)
{
    int i = blockIdx.x * blockDim.x + threadIdx.x;
    if (i >= NN * (DD / 4)) return;
    int c4 = i & (DD / 4 - 1);
    ((float4*)feat)[i] = *(const float4*)(g_biasEff + c4 * 4);
}

__global__ void zero_f_kernel(float* __restrict__ p, int n)
{
    int i = blockIdx.x * blockDim.x + threadIdx.x;
    if (i < n) p[i] = 0.0f;
}

__global__ void zero_i_kernel(int* __restrict__ p, int n)
{
    int i = blockIdx.x * blockDim.x + threadIdx.x;
    if (i < n) p[i] = 0;
}

// ---------------- degrees + CSR build ----------------
__global__ void deg_count_kernel(const int* __restrict__ src, const int* __restrict__ dst)
{
    int i = blockIdx.x * blockDim.x + threadIdx.x;
    if (i < NE) {
        atomicAdd(&g_cs[src[i]], 1.0f);
        atomicAdd(&g_indeg[dst[i]], 1);
    }
}

__global__ void deg_finish_kernel()
{
    int i = blockIdx.x * blockDim.x + threadIdx.x;
    if (i < NN) {
        g_cs[i] = rsqrtf(fmaxf(g_cs[i], 1.0f));
        g_cd[i] = rsqrtf(fmaxf((float)g_indeg[i], 1.0f));
    }
}

// single-block exclusive scan of indeg -> offs (shfl-based, 4 barriers per 1024 tile)
__global__ void scan_offsets_kernel()
{
    __shared__ int wsum[32];
    __shared__ int carryS;
    const int t = threadIdx.x;
    const int lane = t & 31;
    const int w = t >> 5;
    if (t == 0) carryS = 0;
    __syncthreads();
    for (int base = 0; base < NN; base += 1024) {
        int idx = base + t;
        int v = (idx < NN) ? g_indeg[idx] : 0;
        int s = v;
#pragma unroll
        for (int off = 1; off < 32; off <<= 1) {
            int x = __shfl_up_sync(0xffffffffu, s, off);
            if (lane >= off) s += x;
        }
        if (lane == 31) wsum[w] = s;
        __syncthreads();
        if (w == 0) {
            int ws = wsum[lane];
#pragma unroll
            for (int off = 1; off < 32; off <<= 1) {
                int x = __shfl_up_sync(0xffffffffu, ws, off);
                if (lane >= off) ws += x;
            }
            wsum[lane] = ws;
        }
        __syncthreads();
        int wpre = (w == 0) ? 0 : wsum[w - 1];
        int c = carryS;
        if (idx < NN) g_offs[idx] = c + wpre + s - v;
        __syncthreads();
        if (t == 0) carryS = c + wsum[31];
        __syncthreads();
    }
    if (threadIdx.x == 0) g_offs[NN] = carryS;
}

__global__ void bin_edges_kernel(const int* __restrict__ src, const int* __restrict__ dst)
{
    int e = blockIdx.x * blockDim.x + threadIdx.x;
    if (e < NE) {
        int d = dst[e];
        int p = g_offs[d] + atomicAdd(&g_cursor[d], 1);
        g_ein[p] = src[e];
    }
}

// ===== enc GEMM, split-K by modality: red.add partial (feat pre-init with biasEff) =====
#define TBM 128
#define TBN 64
#define TBK 32
#define APW 36
#define BPW 72
#define ENC_SMEM ((2 * TBM * APW + 2 * TBK * BPW) * 4)

__global__ __launch_bounds__(128, 2)
void enc_gemm_kernel(const float* __restrict__ h, const float* __restrict__ Beff,
                     float* __restrict__ C)
{
    extern __shared__ float smem[];
    float* AsBase = smem;
    float* BsBase = smem + 2 * TBM * APW;

    const int t    = threadIdx.x;
    const int warp = t >> 5;
    const int lane = t & 31;
    const int bm   = blockIdx.x * TBM;
    const int m    = blockIdx.y;                 // modality split
    const int wm   = (warp >> 1) * 64;
    const int wn   = (warp & 1) * 32;

    const float* A = h + (size_t)m * NN * DIN;
    const float* B = Beff + (size_t)m * DIN * DD;

    const int aRow = t >> 3;
    const int aCol = (t & 7) * 4;
    const int bRow = t >> 4;
    const int bCol = (t & 15) * 4;

    const int nT = (DIN + TBK - 1) / TBK;        // 63 (last tile partial)

    float4 aReg[8];

    auto ldgA = [&](int k0) {
        const int kk = k0 + aCol;
        const bool kok = (kk + 4 <= DIN);        // DIN % 4 == 0
#pragma unroll
        for (int i = 0; i < 8; i++) {
            int row = bm + aRow + i * 16;
            float4 v = make_float4(0.f, 0.f, 0.f, 0.f);
            if (kok && row < NN)
                v = *(const float4*)(A + (size_t)row * DIN + kk);
            v.x = f2tff(v.x); v.y = f2tff(v.y); v.z = f2tff(v.z); v.w = f2tff(v.w);
            aReg[i] = v;
        }
    };
    auto stsA = [&](int buf) {
        float* As = AsBase + buf * (TBM * APW);
#pragma unroll
        for (int i = 0; i < 8; i++)
            *(float4*)(As + (aRow + i * 16) * APW + aCol) = aReg[i];
    };
    auto cpB = [&](int k0, int buf) {
        float* Bs = BsBase + buf * (TBK * BPW);
#pragma unroll
        for (int i = 0; i < 4; i++) {
            int k = bRow + i * 8;
            int sz = (k0 + k < DIN) ? 16 : 0;
            cp_async16z((uint32_t)__cvta_generic_to_shared(Bs + k * BPW + bCol),
                        B + (size_t)(k0 + k) * DD + bCol, sz);
        }
        asm volatile("cp.async.commit_group;");
    };

    float acc[4][4][4];
#pragma unroll
    for (int mi = 0; mi < 4; mi++)
#pragma unroll
        for (int ni = 0; ni < 4; ni++)
#pragma unroll
            for (int j = 0; j < 4; j++) acc[mi][ni][j] = 0.f;

    ldgA(0);
    cpB(0, 0);

    for (int tt = 0; tt < nT; tt++) {
        const int buf = tt & 1;
        stsA(buf);
        asm volatile("cp.async.wait_group 0;");
        __syncthreads();
        if (tt + 1 < nT) {
            ldgA((tt + 1) * TBK);
            cpB((tt + 1) * TBK, buf ^ 1);
        }

        const float* As = AsBase + buf * (TBM * APW);
        const float* Bs = BsBase + buf * (TBK * BPW);

#pragma unroll
        for (int ks = 0; ks < 4; ks++) {
            const int c = ks * 8 + (lane & 3);
            unsigned bf[4][2];
#pragma unroll
            for (int ni = 0; ni < 4; ni++) {
                int n = wn + ni * 8 + (lane >> 2);
                bf[ni][0] = __float_as_uint(Bs[c * BPW + n]);
                bf[ni][1] = __float_as_uint(Bs[(c + 4) * BPW + n]);
            }
#pragma unroll
            for (int mi = 0; mi < 4; mi++) {
                int r = wm + mi * 16 + (lane >> 2);
                unsigned af[4];
                af[0] = __float_as_uint(As[r * APW + c]);
                af[1] = __float_as_uint(As[(r + 8) * APW + c]);
                af[2] = __float_as_uint(As[r * APW + c + 4]);
                af[3] = __float_as_uint(As[(r + 8) * APW + c + 4]);
#pragma unroll
                for (int ni = 0; ni < 4; ni++)
                    mma_tf32(acc[mi][ni], af, bf[ni]);
            }
        }
        __syncthreads();
    }

    // epilogue: red.add partial into pre-initialized C
#pragma unroll
    for (int mi = 0; mi < 4; mi++) {
        int rbase = bm + wm + mi * 16 + (lane >> 2);
#pragma unroll
        for (int half = 0; half < 2; half++) {
            int row = rbase + half * 8;
            if (row >= NN) continue;
#pragma unroll
            for (int ni = 0; ni < 4; ni++) {
                int col = wn + ni * 8 + 2 * (lane & 3);
                float v0 = acc[mi][ni][half * 2];
                float v1 = acc[mi][ni][half * 2 + 1];
                float* p = C + (size_t)row * DD + col;
                asm volatile("red.global.add.v2.f32 [%0], {%1, %2};"
                             :: "l"(p), "f"(v0), "f"(v1) : "memory");
            }
        }
    }
}

// ---------------- SIMT 64x64 GEMM with batch z (fold + graph layers) ----------------
__global__ __launch_bounds__(256)
void gemm64_kernel(const float* __restrict__ A, const float* __restrict__ B,
                   float* __restrict__ C, int M, int K, int Nc,
                   const float* __restrict__ rowScale, float scalarAlpha,
                   size_t aBStride, size_t bBStride, size_t cBStride)
{
    __shared__ float As[16][64];
    __shared__ float Bs[16][64];

    const float* Az = A + blockIdx.z * aBStride;
    const float* Bz = B + blockIdx.z * bBStride;
    float*       Cz = C + blockIdx.z * cBStride;

    const int t  = threadIdx.x;
    const int bm = blockIdx.y * 64;
    const int bn = blockIdx.x * 64;

    const int a_row = t >> 2;
    const int a_col = (t & 3) * 4;
    const int b_row = t >> 4;
    const int b_col = (t & 15) * 4;

    const int tx = t & 15;
    const int ty = t >> 4;

    float acc[4][4];
#pragma unroll
    for (int i = 0; i < 4; i++)
#pragma unroll
        for (int j = 0; j < 4; j++) acc[i][j] = 0.0f;

    for (int k0 = 0; k0 < K; k0 += 16) {
        float4 av = make_float4(0.f, 0.f, 0.f, 0.f);
        int ar = bm + a_row;
        if (ar < M) {
            if (k0 + a_col + 3 < K) {
                av = *(const float4*)(Az + (size_t)ar * K + k0 + a_col);
            } else {
                float tmp[4] = {0.f, 0.f, 0.f, 0.f};
#pragma unroll
                for (int i = 0; i < 4; i++) {
                    int kk = k0 + a_col + i;
                    if (kk < K) tmp[i] = Az[(size_t)ar * K + kk];
                }
                av = make_float4(tmp[0], tmp[1], tmp[2], tmp[3]);
            }
        }
        As[a_col + 0][a_row] = av.x;
        As[a_col + 1][a_row] = av.y;
        As[a_col + 2][a_row] = av.z;
        As[a_col + 3][a_row] = av.w;

        float4 bv = make_float4(0.f, 0.f, 0.f, 0.f);
        int brr = k0 + b_row;
        int bcc = bn + b_col;
        if (brr < K) {
            if (bcc + 3 < Nc) {
                bv = *(const float4*)(Bz + (size_t)brr * Nc + bcc);
            } else {
                float tmp[4] = {0.f, 0.f, 0.f, 0.f};
#pragma unroll
                for (int i = 0; i < 4; i++) {
                    int cc = bcc + i;
                    if (cc < Nc) tmp[i] = Bz[(size_t)brr * Nc + cc];
                }
                bv = make_float4(tmp[0], tmp[1], tmp[2], tmp[3]);
            }
        }
        *(float4*)&Bs[b_row][b_col] = bv;

        __syncthreads();

#pragma unroll
        for (int k = 0; k < 16; k++) {
            float4 a = *(const float4*)&As[k][ty * 4];
            float4 b = *(const float4*)&Bs[k][tx * 4];
            acc[0][0] += a.x * b.x; acc[0][1] += a.x * b.y; acc[0][2] += a.x * b.z; acc[0][3] += a.x * b.w;
            acc[1][0] += a.y * b.x; acc[1][1] += a.y * b.y; acc[1][2] += a.y * b.z; acc[1][3] += a.y * b.w;
            acc[2][0] += a.z * b.x; acc[2][1] += a.z * b.y; acc[2][2] += a.z * b.z; acc[2][3] += a.z * b.w;
            acc[3][0] += a.w * b.x; acc[3][1] += a.w * b.y; acc[3][2] += a.w * b.z; acc[3][3] += a.w * b.w;
        }
        __syncthreads();
    }

#pragma unroll
    for (int i = 0; i < 4; i++) {
        int row = bm + ty * 4 + i;
        if (row >= M) continue;
        float rs = rowScale ? rowScale[row] : scalarAlpha;
#pragma unroll
        for (int j = 0; j < 4; j++) {
            int col = bn + tx * 4 + j;
            if (col >= Nc) continue;
            Cz[(size_t)row * Nc + col] = acc[i][j] * rs;
        }
    }
}

// ---------------- CSR gather-aggregate, fused cd*agg + bias (+relu), 4-way unroll ----------------
__global__ void gather64_kernel(const float* __restrict__ xw, float* __restrict__ out,
                                const float* __restrict__ bias)
{
    int node = blockIdx.x * (blockDim.x >> 5) + (threadIdx.x >> 5);
    if (node >= NN) return;
    int lane = threadIdx.x & 31;
    int beg = g_offs[node], end = g_offs[node + 1];
    float ax = 0.f, ay = 0.f;
    int e = beg;
    for (; e + 4 <= end; e += 4) {
        int s0 = g_ein[e], s1 = g_ein[e + 1], s2 = g_ein[e + 2], s3 = g_ein[e + 3];
        float2 v0 = *(const float2*)(xw + (size_t)s0 * 64 + lane * 2);
        float2 v1 = *(const float2*)(xw + (size_t)s1 * 64 + lane * 2);
        float2 v2 = *(const float2*)(xw + (size_t)s2 * 64 + lane * 2);
        float2 v3 = *(const float2*)(xw + (size_t)s3 * 64 + lane * 2);
        ax += (v0.x + v1.x) + (v2.x + v3.x);
        ay += (v0.y + v1.y) + (v2.y + v3.y);
    }
    for (; e < end; e++) {
        float2 v = *(const float2*)(xw + (size_t)g_ein[e] * 64 + lane * 2);
        ax += v.x; ay += v.y;
    }
    float cdv = g_cd[node];
    float o0 = fmaxf(ax * cdv + bias[lane * 2], 0.f);
    float o1 = fmaxf(ay * cdv + bias[lane * 2 + 1], 0.f);
    *(float2*)(out + (size_t)node * 64 + lane * 2) = make_float2(o0, o1);
}

__global__ void gather32_kernel(const float* __restrict__ xw, float* __restrict__ out,
                                const float* __restrict__ bias)
{
    int node = blockIdx.x * (blockDim.x >> 5) + (threadIdx.x >> 5);
    if (node >= NN) return;
    int lane = threadIdx.x & 31;
    int beg = g_offs[node], end = g_offs[node + 1];
    float a = 0.f;
    int e = beg;
    for (; e + 4 <= end; e += 4) {
        int s0 = g_ein[e], s1 = g_ein[e + 1], s2 = g_ein[e + 2], s3 = g_ein[e + 3];
        float v0 = xw[(size_t)s0 * 32 + lane];
        float v1 = xw[(size_t)s1 * 32 + lane];
        float v2 = xw[(size_t)s2 * 32 + lane];
        float v3 = xw[(size_t)s3 * 32 + lane];
        a += (v0 + v1) + (v2 + v3);
    }
    for (; e < end; e++)
        a += xw[(size_t)g_ein[e] * 32 + lane];
    out[(size_t)node * 32 + lane] = fmaxf(a * g_cd[node] + bias[lane], 0.f);
}

__global__ void gather4_kernel(const float* __restrict__ xw, float* __restrict__ out,
                               const float* __restrict__ bias)
{
    int node = blockIdx.x * blockDim.x + threadIdx.x;
    if (node >= NN) return;
    int beg = g_offs[node], end = g_offs[node + 1];
    float4 a = make_float4(0.f, 0.f, 0.f, 0.f);
    int e = beg;
    for (; e + 4 <= end; e += 4) {
        int s0 = g_ein[e], s1 = g_ein[e + 1], s2 = g_ein[e + 2], s3 = g_ein[e + 3];
        float4 v0 = *(const float4*)(xw + (size_t)s0 * 4);
        float4 v1 = *(const float4*)(xw + (size_t)s1 * 4);
        float4 v2 = *(const float4*)(xw + (size_t)s2 * 4);
        float4 v3 = *(const float4*)(xw + (size_t)s3 * 4);
        a.x += (v0.x + v1.x) + (v2.x + v3.x);
        a.y += (v0.y + v1.y) + (v2.y + v3.y);
        a.z += (v0.z + v1.z) + (v2.z + v3.z);
        a.w += (v0.w + v1.w) + (v2.w + v3.w);
    }
    for (; e < end; e++) {
        float4 v = *(const float4*)(xw + (size_t)g_ein[e] * 4);
        a.x += v.x; a.y += v.y; a.z += v.z; a.w += v.w;
    }
    float cdv = g_cd[node];
    a.x = a.x * cdv + bias[0];
    a.y = a.y * cdv + bias[1];
    a.z = a.z * cdv + bias[2];
    a.w = a.w * cdv + bias[3];
    *(float4*)(out + (size_t)node * 4) = a;
}

// ---------------- launch ----------------
static inline dim3 gemm_grid(int M, int Nc, int z)
{
    return dim3((Nc + 63) / 64, (M + 63) / 64, z);
}

extern "C" void kernel_launch(void* const* d_in, const int* in_sizes, int n_in,
                              void* d_out, int out_size)
{
    const float* h   = (const float*)d_in[0];
    const int*   src = (const int*)  d_in[1];
    const int*   dst = (const int*)  d_in[2];
    const float* W1  = (const float*)d_in[3];
    const float* b1  = (const float*)d_in[4];
    const float* g1  = (const float*)d_in[5];
    const float* be1 = (const float*)d_in[6];
    const float* m1  = (const float*)d_in[7];
    const float* v1  = (const float*)d_in[8];
    const float* W2  = (const float*)d_in[9];
    const float* b2  = (const float*)d_in[10];
    const float* g2  = (const float*)d_in[11];
    const float* be2 = (const float*)d_in[12];
    const float* m2  = (const float*)d_in[13];
    const float* v2  = (const float*)d_in[14];
    const float* Wd  = (const float*)d_in[15];
    const float* bd  = (const float*)d_in[16];
    const float* Wg0 = (const float*)d_in[17];
    const float* bg0 = (const float*)d_in[18];
    const float* Wg1 = (const float*)d_in[19];
    const float* bg1 = (const float*)d_in[20];
    const float* Wg2 = (const float*)d_in[21];
    const float* bg2 = (const float*)d_in[22];
    float* out = (float*)d_out;

    float *w2s, *wds, *t2, *beff, *biasEff;
    float *feat, *xw, *y1, *y2, *cs, *cd, *alpha1, *alpha2;
    int *indeg, *cursor;
    cudaGetSymbolAddress((void**)&w2s, g_w2s);
    cudaGetSymbolAddress((void**)&wds, g_wds);
    cudaGetSymbolAddress((void**)&t2, g_t2);
    cudaGetSymbolAddress((void**)&beff, g_beff);
    cudaGetSymbolAddress((void**)&biasEff, g_biasEff);
    cudaGetSymbolAddress((void**)&feat, g_feat);
    cudaGetSymbolAddress((void**)&xw, g_xw);
    cudaGetSymbolAddress((void**)&y1, g_y1);
    cudaGetSymbolAddress((void**)&y2, g_y2);
    cudaGetSymbolAddress((void**)&cs, g_cs);
    cudaGetSymbolAddress((void**)&cd, g_cd);
    cudaGetSymbolAddress((void**)&alpha1, g_alpha1);
    cudaGetSymbolAddress((void**)&alpha2, g_alpha2);
    cudaGetSymbolAddress((void**)&indeg, g_indeg);
    cudaGetSymbolAddress((void**)&cursor, g_cursor);

    cudaFuncSetAttribute(enc_gemm_kernel, cudaFuncAttributeMaxDynamicSharedMemorySize, ENC_SMEM);

    // --- fold the linear encoder into Beff [4000][64] + biasEff [64] ---
    prep_kernel<<<1, 512>>>(b1, g1, be1, m1, v1, b2, g2, be2, m2, v2);
    {
        int n = 2 * H1 * H2;
        scale_rows_kernel<<<(n + 255) / 256, 256>>>(W2, alpha1, w2s, 2 * H1, H2);
        n = 2 * H2 * DD;
        scale_rows_kernel<<<(n + 255) / 256, 256>>>(Wd, alpha2, wds, 2 * H2, DD);
    }
    gemm64_kernel<<<gemm_grid(H1, DD, 2), 256>>>(
        w2s, wds, t2, H1, H2, DD, nullptr, 1.0f,
        (size_t)H1 * H2, (size_t)H2 * DD, (size_t)H1 * DD);
    gemm64_kernel<<<gemm_grid(DIN, DD, 2), 256>>>(
        W1, t2, beff, DIN, H1, DD, nullptr, 0.5f,
        (size_t)DIN * H1, (size_t)H1 * DD, (size_t)DIN * DD);
    round_tf32_kernel<<<(KTOT * DD / 4 + 255) / 256, 256>>>(beff, KTOT * DD / 4);
    bias_chain_kernel<<<1, 128>>>(W2, b2, Wd, bd);

    // --- degrees + CSR ---
    zero_f_kernel<<<(NN + 255) / 256, 256>>>(cs, NN);
    zero_i_kernel<<<(NN + 255) / 256, 256>>>(indeg, NN);
    zero_i_kernel<<<(NN + 255) / 256, 256>>>(cursor, NN);
    deg_count_kernel<<<(NE + 255) / 256, 256>>>(src, dst);
    deg_finish_kernel<<<(NN + 255) / 256, 256>>>();
    scan_offsets_kernel<<<1, 1024>>>();
    bin_edges_kernel<<<(NE + 255) / 256, 256>>>(src, dst);

    // --- collapsed encoder: feat = biasEff + sum_m h_m @ Beff_m (split-K, red.add) ---
    init_feat_kernel<<<(NN * (DD / 4) + 255) / 256, 256>>>(feat);
    enc_gemm_kernel<<<dim3((NN + TBM - 1) / TBM, 2), 128, ENC_SMEM>>>(h, beff, feat);

    // ---- GraphConv 1: 64 -> 64, relu ----
    gemm64_kernel<<<gemm_grid(NN, DD, 1), 256>>>(feat, Wg0, xw, NN, DD, DD, cs, 1.0f, 0, 0, 0);
    gather64_kernel<<<(NN * 32 + 255) / 256, 256>>>(xw, y1, bg0);

    // ---- GraphConv 2: 64 -> 32, relu ----
    gemm64_kernel<<<gemm_grid(NN, 32, 1), 256>>>(y1, Wg1, xw, NN, DD, 32, cs, 1.0f, 0, 0, 0);
    gather32_kernel<<<(NN * 32 + 255) / 256, 256>>>(xw, y2, bg1);

    // ---- GraphConv 3: 32 -> 4, no relu, write output ----
    gemm64_kernel<<<gemm_grid(NN, 4, 1), 256>>>(y2, Wg2, xw, NN, 32, 4, cs, 1.0f, 0, 0, 0);
    gather4_kernel<<<(NN + 255) / 256, 256>>>(xw, out, bg2);
}

// round 13
// speedup vs baseline: 5.2533x; 1.2199x over previous
#include <cuda_runtime.h>
#include <cstdint>

#define NN   50000
#define NE   1600000
#define DIN  2000
#define H1   500
#define H2   128
#define DD   64
#define KTOT (2 * DIN)   // 4000

// ---------------- scratch (static device globals; no allocation) ----------------
static __device__ float g_w2s[2 * H1 * H2];     // alpha1-scaled W2
static __device__ float g_wds[2 * H2 * DD];     // alpha2-scaled Wd
static __device__ float g_t2[2 * H1 * DD];      // W2s @ Wds
static __device__ float g_beff[KTOT * DD];      // [4000][64] effective weights
static __device__ float g_biasEff[DD];
static __device__ float g_feat[NN * DD];
static __device__ float g_xw[NN * DD];
static __device__ float g_y1[NN * DD];
static __device__ float g_y2[NN * 32];
static __device__ float g_cs[NN];
static __device__ float g_cd[NN];
static __device__ int   g_indeg[NN];
static __device__ int   g_offs[NN + 1];
static __device__ int   g_cursor[NN];
static __device__ int   g_ein[NE];              // edge src ids grouped by dst
static __device__ float g_alpha1[2 * H1], g_beta1[2 * H1];
static __device__ float g_alpha2[2 * H2], g_beta2[2 * H2];

// ---------------- helpers ----------------
__device__ __forceinline__ void mma_tf32(float* c, const unsigned* a, const unsigned* b)
{
    asm volatile(
        "mma.sync.aligned.m16n8k8.row.col.f32.tf32.tf32.f32 "
        "{%0,%1,%2,%3}, {%4,%5,%6,%7}, {%8,%9}, {%0,%1,%2,%3};\n"
        : "+f"(c[0]), "+f"(c[1]), "+f"(c[2]), "+f"(c[3])
        : "r"(a[0]), "r"(a[1]), "r"(a[2]), "r"(a[3]), "r"(b[0]), "r"(b[1]));
}

__device__ __forceinline__ void cp_async16z(uint32_t dst, const void* src, int sz)
{
    asm volatile("cp.async.cg.shared.global [%0], [%1], 16, %2;"
                 :: "r"(dst), "l"(src), "r"(sz));
}

// ---------------- prep: BN fold vectors ----------------
__global__ void prep_kernel(const float* __restrict__ b1, const float* __restrict__ g1,
                            const float* __restrict__ be1, const float* __restrict__ m1,
                            const float* __restrict__ v1,
                            const float* __restrict__ b2, const float* __restrict__ g2,
                            const float* __restrict__ be2, const float* __restrict__ m2,
                            const float* __restrict__ v2)
{
    int t = threadIdx.x;
    for (int i = t; i < 2 * H1; i += blockDim.x) {
        float a = g1[i] * rsqrtf(v1[i] + 1e-5f);
        g_alpha1[i] = a;
        g_beta1[i]  = (b1[i] - m1[i]) * a + be1[i];
    }
    for (int i = t; i < 2 * H2; i += blockDim.x) {
        float a = g2[i] * rsqrtf(v2[i] + 1e-5f);
        g_alpha2[i] = a;
        g_beta2[i]  = (b2[i] - m2[i]) * a + be2[i];
    }
}

__global__ void scale_rows_kernel(const float* __restrict__ W, const float* __restrict__ scale,
                                  float* __restrict__ out, int K, int N)
{
    int idx = blockIdx.x * blockDim.x + threadIdx.x;
    if (idx >= K * N) return;
    int k = idx / N;
    out[idx] = scale[k] * W[idx];
}

__global__ void bias_chain_kernel(const float* __restrict__ W2, const float* __restrict__ b2,
                                  const float* __restrict__ Wd, const float* __restrict__ bd)
{
    __shared__ float v[2][H2];
    int t = threadIdx.x;   // 128 threads
    for (int m = 0; m < 2; m++) {
        float u = b2[m * H2 + t];
        for (int k = 0; k < H1; k++)
            u += g_beta1[m * H1 + k] * W2[(size_t)m * H1 * H2 + k * H2 + t];
        v[m][t] = u * g_alpha2[m * H2 + t] + g_beta2[m * H2 + t];
    }
    __syncthreads();
    if (t < DD) {
        float s = 0.f;
        for (int m = 0; m < 2; m++) {
            float tmp = bd[m * DD + t];
            for (int n = 0; n < H2; n++)
                tmp += v[m][n] * Wd[(size_t)m * H2 * DD + n * DD + t];
            s += 0.5f * tmp;
        }
        g_biasEff[t] = s;
    }
}

// feat[n][c] = biasEff[c]  (float4 granularity)
__global__ void init_feat_kernel(float* __restrict__ feat)
{
    int i = blockIdx.x * blockDim.x + threadIdx.x;
    if (i >= NN * (DD / 4)) return;
    int c4 = i & (DD / 4 - 1);
    ((float4*)feat)[i] = *(const float4*)(g_biasEff + c4 * 4);
}

// zero cs (float), indeg, cursor (int) in one pass
__global__ void zero_csr_kernel()
{
    int i = blockIdx.x * blockDim.x + threadIdx.x;
    if (i < NN) {
        g_cs[i] = 0.0f;
        g_indeg[i] = 0;
        g_cursor[i] = 0;
    }
}

// ---------------- degrees + CSR build ----------------
__global__ void deg_count_kernel(const int* __restrict__ src, const int* __restrict__ dst)
{
    int i = blockIdx.x * blockDim.x + threadIdx.x;
    if (i < NE) {
        atomicAdd(&g_cs[src[i]], 1.0f);
        atomicAdd(&g_indeg[dst[i]], 1);
    }
}

__global__ void deg_finish_kernel()
{
    int i = blockIdx.x * blockDim.x + threadIdx.x;
    if (i < NN) {
        g_cs[i] = rsqrtf(fmaxf(g_cs[i], 1.0f));
        g_cd[i] = rsqrtf(fmaxf((float)g_indeg[i], 1.0f));
    }
}

// single-block exclusive scan of indeg -> offs (shfl-based)
__global__ void scan_offsets_kernel()
{
    __shared__ int wsum[32];
    __shared__ int carryS;
    const int t = threadIdx.x;
    const int lane = t & 31;
    const int w = t >> 5;
    if (t == 0) carryS = 0;
    __syncthreads();
    for (int base = 0; base < NN; base += 1024) {
        int idx = base + t;
        int v = (idx < NN) ? g_indeg[idx] : 0;
        int s = v;
#pragma unroll
        for (int off = 1; off < 32; off <<= 1) {
            int x = __shfl_up_sync(0xffffffffu, s, off);
            if (lane >= off) s += x;
        }
        if (lane == 31) wsum[w] = s;
        __syncthreads();
        if (w == 0) {
            int ws = wsum[lane];
#pragma unroll
            for (int off = 1; off < 32; off <<= 1) {
                int x = __shfl_up_sync(0xffffffffu, ws, off);
                if (lane >= off) ws += x;
            }
            wsum[lane] = ws;
        }
        __syncthreads();
        int wpre = (w == 0) ? 0 : wsum[w - 1];
        int c = carryS;
        if (idx < NN) g_offs[idx] = c + wpre + s - v;
        __syncthreads();
        if (t == 0) carryS = c + wsum[31];
        __syncthreads();
    }
    if (threadIdx.x == 0) g_offs[NN] = carryS;
}

__global__ void bin_edges_kernel(const int* __restrict__ src, const int* __restrict__ dst)
{
    int e = blockIdx.x * blockDim.x + threadIdx.x;
    if (e < NE) {
        int d = dst[e];
        int p = g_offs[d] + atomicAdd(&g_cursor[d], 1);
        g_ein[p] = src[e];
    }
}

// ===== enc GEMM: split-K by modality, full cp.async 3-stage, raw-fp32 tf32 (truncation) =====
#define TBM 128
#define TBN 64
#define TBK 32
#define APW 36
#define BPW 72
#define STG_WORDS (TBM * APW + TBK * BPW)
#define ENC_SMEM (3 * STG_WORDS * 4)

__global__ __launch_bounds__(128, 2)
void enc_gemm_kernel(const float* __restrict__ h, const float* __restrict__ Beff,
                     float* __restrict__ C)
{
    extern __shared__ float smem[];

    const int t    = threadIdx.x;
    const int warp = t >> 5;
    const int lane = t & 31;
    const int bm   = blockIdx.x * TBM;
    const int m    = blockIdx.y;                 // modality split
    const int wm   = (warp >> 1) * 64;
    const int wn   = (warp & 1) * 32;

    const float* A = h + (size_t)m * NN * DIN;
    const float* B = Beff + (size_t)m * DIN * DD;

    const int aRow = t >> 3;             // 0..15, 8 passes of 16 rows
    const int aCol = (t & 7) * 4;        // 0..28
    const int bRow = t >> 4;             // 0..7, 4 passes of 8 k-rows
    const int bCol = (t & 15) * 4;       // 0..60

    const int nT = (DIN + TBK - 1) / TBK;        // 63 (last tile partial)

    auto issueAB = [&](int tt) {
        const int k0 = tt * TBK;
        float* As = smem + (tt % 3) * STG_WORDS;
        float* Bs = As + TBM * APW;
        const int kk = k0 + aCol;
        const int aok = (kk + 4 <= DIN);
#pragma unroll
        for (int i = 0; i < 8; i++) {
            int row = bm + aRow + i * 16;
            int sz = (aok && row < NN) ? 16 : 0;
            cp_async16z((uint32_t)__cvta_generic_to_shared(As + (aRow + i * 16) * APW + aCol),
                        A + (size_t)row * DIN + kk, sz);
        }
#pragma unroll
        for (int i = 0; i < 4; i++) {
            int k = bRow + i * 8;
            int sz = (k0 + k < DIN) ? 16 : 0;
            cp_async16z((uint32_t)__cvta_generic_to_shared(Bs + k * BPW + bCol),
                        B + (size_t)(k0 + k) * DD + bCol, sz);
        }
        asm volatile("cp.async.commit_group;");
    };

    float acc[4][4][4];
#pragma unroll
    for (int mi = 0; mi < 4; mi++)
#pragma unroll
        for (int ni = 0; ni < 4; ni++)
#pragma unroll
            for (int j = 0; j < 4; j++) acc[mi][ni][j] = 0.f;

    issueAB(0);
    issueAB(1);

    for (int tt = 0; tt < nT; tt++) {
        if (tt + 2 < nT) {
            issueAB(tt + 2);
            asm volatile("cp.async.wait_group 2;");
        } else if (tt + 1 < nT) {
            asm volatile("cp.async.wait_group 1;");
        } else {
            asm volatile("cp.async.wait_group 0;");
        }
        __syncthreads();

        const float* As = smem + (tt % 3) * STG_WORDS;
        const float* Bs = As + TBM * APW;

#pragma unroll
        for (int ks = 0; ks < 4; ks++) {
            const int c = ks * 8 + (lane & 3);
            unsigned bf[4][2];
#pragma unroll
            for (int ni = 0; ni < 4; ni++) {
                int n = wn + ni * 8 + (lane >> 2);
                bf[ni][0] = __float_as_uint(Bs[c * BPW + n]);
                bf[ni][1] = __float_as_uint(Bs[(c + 4) * BPW + n]);
            }
#pragma unroll
            for (int mi = 0; mi < 4; mi++) {
                int r = wm + mi * 16 + (lane >> 2);
                unsigned af[4];
                af[0] = __float_as_uint(As[r * APW + c]);
                af[1] = __float_as_uint(As[(r + 8) * APW + c]);
                af[2] = __float_as_uint(As[r * APW + c + 4]);
                af[3] = __float_as_uint(As[(r + 8) * APW + c + 4]);
#pragma unroll
                for (int ni = 0; ni < 4; ni++)
                    mma_tf32(acc[mi][ni], af, bf[ni]);
            }
        }
        __syncthreads();
    }

    // epilogue: red.add partial into pre-initialized C
#pragma unroll
    for (int mi = 0; mi < 4; mi++) {
        int rbase = bm + wm + mi * 16 + (lane >> 2);
#pragma unroll
        for (int half = 0; half < 2; half++) {
            int row = rbase + half * 8;
            if (row >= NN) continue;
#pragma unroll
            for (int ni = 0; ni < 4; ni++) {
                int col = wn + ni * 8 + 2 * (lane & 3);
                float v0 = acc[mi][ni][half * 2];
                float v1 = acc[mi][ni][half * 2 + 1];
                float* p = C + (size_t)row * DD + col;
                asm volatile("red.global.add.v2.f32 [%0], {%1, %2};"
                             :: "l"(p), "f"(v0), "f"(v1) : "memory");
            }
        }
    }
}

// ---------------- SIMT 64x64 GEMM with batch z (fold + graph layers) ----------------
__global__ __launch_bounds__(256)
void gemm64_kernel(const float* __restrict__ A, const float* __restrict__ B,
                   float* __restrict__ C, int M, int K, int Nc,
                   const float* __restrict__ rowScale, float scalarAlpha,
                   size_t aBStride, size_t bBStride, size_t cBStride)
{
    __shared__ float As[16][64];
    __shared__ float Bs[16][64];

    const float* Az = A + blockIdx.z * aBStride;
    const float* Bz = B + blockIdx.z * bBStride;
    float*       Cz = C + blockIdx.z * cBStride;

    const int t  = threadIdx.x;
    const int bm = blockIdx.y * 64;
    const int bn = blockIdx.x * 64;

    const int a_row = t >> 2;
    const int a_col = (t & 3) * 4;
    const int b_row = t >> 4;
    const int b_col = (t & 15) * 4;

    const int tx = t & 15;
    const int ty = t >> 4;

    float acc[4][4];
#pragma unroll
    for (int i = 0; i < 4; i++)
#pragma unroll
        for (int j = 0; j < 4; j++) acc[i][j] = 0.0f;

    for (int k0 = 0; k0 < K; k0 += 16) {
        float4 av = make_float4(0.f, 0.f, 0.f, 0.f);
        int ar = bm + a_row;
        if (ar < M) {
            if (k0 + a_col + 3 < K) {
                av = *(const float4*)(Az + (size_t)ar * K + k0 + a_col);
            } else {
                float tmp[4] = {0.f, 0.f, 0.f, 0.f};
#pragma unroll
                for (int i = 0; i < 4; i++) {
                    int kk = k0 + a_col + i;
                    if (kk < K) tmp[i] = Az[(size_t)ar * K + kk];
                }
                av = make_float4(tmp[0], tmp[1], tmp[2], tmp[3]);
            }
        }
        As[a_col + 0][a_row] = av.x;
        As[a_col + 1][a_row] = av.y;
        As[a_col + 2][a_row] = av.z;
        As[a_col + 3][a_row] = av.w;

        float4 bv = make_float4(0.f, 0.f, 0.f, 0.f);
        int brr = k0 + b_row;
        int bcc = bn + b_col;
        if (brr < K) {
            if (bcc + 3 < Nc) {
                bv = *(const float4*)(Bz + (size_t)brr * Nc + bcc);
            } else {
                float tmp[4] = {0.f, 0.f, 0.f, 0.f};
#pragma unroll
                for (int i = 0; i < 4; i++) {
                    int cc = bcc + i;
                    if (cc < Nc) tmp[i] = Bz[(size_t)brr * Nc + cc];
                }
                bv = make_float4(tmp[0], tmp[1], tmp[2], tmp[3]);
            }
        }
        *(float4*)&Bs[b_row][b_col] = bv;

        __syncthreads();

#pragma unroll
        for (int k = 0; k < 16; k++) {
            float4 a = *(const float4*)&As[k][ty * 4];
            float4 b = *(const float4*)&Bs[k][tx * 4];
            acc[0][0] += a.x * b.x; acc[0][1] += a.x * b.y; acc[0][2] += a.x * b.z; acc[0][3] += a.x * b.w;
            acc[1][0] += a.y * b.x; acc[1][1] += a.y * b.y; acc[1][2] += a.y * b.z; acc[1][3] += a.y * b.w;
            acc[2][0] += a.z * b.x; acc[2][1] += a.z * b.y; acc[2][2] += a.z * b.z; acc[2][3] += a.z * b.w;
            acc[3][0] += a.w * b.x; acc[3][1] += a.w * b.y; acc[3][2] += a.w * b.z; acc[3][3] += a.w * b.w;
        }
        __syncthreads();
    }

#pragma unroll
    for (int i = 0; i < 4; i++) {
        int row = bm + ty * 4 + i;
        if (row >= M) continue;
        float rs = rowScale ? rowScale[row] : scalarAlpha;
#pragma unroll
        for (int j = 0; j < 4; j++) {
            int col = bn + tx * 4 + j;
            if (col >= Nc) continue;
            Cz[(size_t)row * Nc + col] = acc[i][j] * rs;
        }
    }
}

// ---------------- CSR gather-aggregate, fused cd*agg + bias (+relu), 4-way unroll ----------------
__global__ void gather64_kernel(const float* __restrict__ xw, float* __restrict__ out,
                                const float* __restrict__ bias)
{
    int node = blockIdx.x * (blockDim.x >> 5) + (threadIdx.x >> 5);
    if (node >= NN) return;
    int lane = threadIdx.x & 31;
    int beg = g_offs[node], end = g_offs[node + 1];
    float ax = 0.f, ay = 0.f;
    int e = beg;
    for (; e + 4 <= end; e += 4) {
        int s0 = g_ein[e], s1 = g_ein[e + 1], s2 = g_ein[e + 2], s3 = g_ein[e + 3];
        float2 v0 = *(const float2*)(xw + (size_t)s0 * 64 + lane * 2);
        float2 v1 = *(const float2*)(xw + (size_t)s1 * 64 + lane * 2);
        float2 v2 = *(const float2*)(xw + (size_t)s2 * 64 + lane * 2);
        float2 v3 = *(const float2*)(xw + (size_t)s3 * 64 + lane * 2);
        ax += (v0.x + v1.x) + (v2.x + v3.x);
        ay += (v0.y + v1.y) + (v2.y + v3.y);
    }
    for (; e < end; e++) {
        float2 v = *(const float2*)(xw + (size_t)g_ein[e] * 64 + lane * 2);
        ax += v.x; ay += v.y;
    }
    float cdv = g_cd[node];
    float o0 = fmaxf(ax * cdv + bias[lane * 2], 0.f);
    float o1 = fmaxf(ay * cdv + bias[lane * 2 + 1], 0.f);
    *(float2*)(out + (size_t)node * 64 + lane * 2) = make_float2(o0, o1);
}

__global__ void gather32_kernel(const float* __restrict__ xw, float* __restrict__ out,
                                const float* __restrict__ bias)
{
    int node = blockIdx.x * (blockDim.x >> 5) + (threadIdx.x >> 5);
    if (node >= NN) return;
    int lane = threadIdx.x & 31;
    int beg = g_offs[node], end = g_offs[node + 1];
    float a = 0.f;
    int e = beg;
    for (; e + 4 <= end; e += 4) {
        int s0 = g_ein[e], s1 = g_ein[e + 1], s2 = g_ein[e + 2], s3 = g_ein[e + 3];
        float v0 = xw[(size_t)s0 * 32 + lane];
        float v1 = xw[(size_t)s1 * 32 + lane];
        float v2 = xw[(size_t)s2 * 32 + lane];
        float v3 = xw[(size_t)s3 * 32 + lane];
        a += (v0 + v1) + (v2 + v3);
    }
    for (; e < end; e++)
        a += xw[(size_t)g_ein[e] * 32 + lane];
    out[(size_t)node * 32 + lane] = fmaxf(a * g_cd[node] + bias[lane], 0.f);
}

__global__ void gather4_kernel(const float* __restrict__ xw, float* __restrict__ out,
                               const float* __restrict__ bias)
{
    int node = blockIdx.x * blockDim.x + threadIdx.x;
    if (node >= NN) return;
    int beg = g_offs[node], end = g_offs[node + 1];
    float4 a = make_float4(0.f, 0.f, 0.f, 0.f);
    int e = beg;
    for (; e + 4 <= end; e += 4) {
        int s0 = g_ein[e], s1 = g_ein[e + 1], s2 = g_ein[e + 2], s3 = g_ein[e + 3];
        float4 v0 = *(const float4*)(xw + (size_t)s0 * 4);
        float4 v1 = *(const float4*)(xw + (size_t)s1 * 4);
        float4 v2 = *(const float4*)(xw + (size_t)s2 * 4);
        float4 v3 = *(const float4*)(xw + (size_t)s3 * 4);
        a.x += (v0.x + v1.x) + (v2.x + v3.x);
        a.y += (v0.y + v1.y) + (v2.y + v3.y);
        a.z += (v0.z + v1.z) + (v2.z + v3.z);
        a.w += (v0.w + v1.w) + (v2.w + v3.w);
    }
    for (; e < end; e++) {
        float4 v = *(const float4*)(xw + (size_t)g_ein[e] * 4);
        a.x += v.x; a.y += v.y; a.z += v.z; a.w += v.w;
    }
    float cdv = g_cd[node];
    a.x = a.x * cdv + bias[0];
    a.y = a.y * cdv + bias[1];
    a.z = a.z * cdv + bias[2];
    a.w = a.w * cdv + bias[3];
    *(float4*)(out + (size_t)node * 4) = a;
}

// ---------------- launch ----------------
static inline dim3 gemm_grid(int M, int Nc, int z)
{
    return dim3((Nc + 63) / 64, (M + 63) / 64, z);
}

extern "C" void kernel_launch(void* const* d_in, const int* in_sizes, int n_in,
                              void* d_out, int out_size)
{
    const float* h   = (const float*)d_in[0];
    const int*   src = (const int*)  d_in[1];
    const int*   dst = (const int*)  d_in[2];
    const float* W1  = (const float*)d_in[3];
    const float* b1  = (const float*)d_in[4];
    const float* g1  = (const float*)d_in[5];
    const float* be1 = (const float*)d_in[6];
    const float* m1  = (const float*)d_in[7];
    const float* v1  = (const float*)d_in[8];
    const float* W2  = (const float*)d_in[9];
    const float* b2  = (const float*)d_in[10];
    const float* g2  = (const float*)d_in[11];
    const float* be2 = (const float*)d_in[12];
    const float* m2  = (const float*)d_in[13];
    const float* v2  = (const float*)d_in[14];
    const float* Wd  = (const float*)d_in[15];
    const float* bd  = (const float*)d_in[16];
    const float* Wg0 = (const float*)d_in[17];
    const float* bg0 = (const float*)d_in[18];
    const float* Wg1 = (const float*)d_in[19];
    const float* bg1 = (const float*)d_in[20];
    const float* Wg2 = (const float*)d_in[21];
    const float* bg2 = (const float*)d_in[22];
    float* out = (float*)d_out;

    float *w2s, *wds, *t2, *beff;
    float *feat, *xw, *y1, *y2, *cs, *alpha1, *alpha2;
    cudaGetSymbolAddress((void**)&w2s, g_w2s);
    cudaGetSymbolAddress((void**)&wds, g_wds);
    cudaGetSymbolAddress((void**)&t2, g_t2);
    cudaGetSymbolAddress((void**)&beff, g_beff);
    cudaGetSymbolAddress((void**)&feat, g_feat);
    cudaGetSymbolAddress((void**)&xw, g_xw);
    cudaGetSymbolAddress((void**)&y1, g_y1);
    cudaGetSymbolAddress((void**)&y2, g_y2);
    cudaGetSymbolAddress((void**)&cs, g_cs);
    cudaGetSymbolAddress((void**)&alpha1, g_alpha1);
    cudaGetSymbolAddress((void**)&alpha2, g_alpha2);

    cudaFuncSetAttribute(enc_gemm_kernel, cudaFuncAttributeMaxDynamicSharedMemorySize, ENC_SMEM);

    // --- fold the linear encoder into Beff [4000][64] + biasEff [64] ---
    prep_kernel<<<1, 512>>>(b1, g1, be1, m1, v1, b2, g2, be2, m2, v2);
    {
        int n = 2 * H1 * H2;
        scale_rows_kernel<<<(n + 255) / 256, 256>>>(W2, alpha1, w2s, 2 * H1, H2);
        n = 2 * H2 * DD;
        scale_rows_kernel<<<(n + 255) / 256, 256>>>(Wd, alpha2, wds, 2 * H2, DD);
    }
    gemm64_kernel<<<gemm_grid(H1, DD, 2), 256>>>(
        w2s, wds, t2, H1, H2, DD, nullptr, 1.0f,
        (size_t)H1 * H2, (size_t)H2 * DD, (size_t)H1 * DD);
    gemm64_kernel<<<gemm_grid(DIN, DD, 2), 256>>>(
        W1, t2, beff, DIN, H1, DD, nullptr, 0.5f,
        (size_t)DIN * H1, (size_t)H1 * DD, (size_t)DIN * DD);
    bias_chain_kernel<<<1, 128>>>(W2, b2, Wd, bd);

    // --- degrees + CSR ---
    zero_csr_kernel<<<(NN + 255) / 256, 256>>>();
    deg_count_kernel<<<(NE + 255) / 256, 256>>>(src, dst);
    deg_finish_kernel<<<(NN + 255) / 256, 256>>>();
    scan_offsets_kernel<<<1, 1024>>>();
    bin_edges_kernel<<<(NE + 255) / 256, 256>>>(src, dst);

    // --- collapsed encoder: feat = biasEff + sum_m h_m @ Beff_m (split-K, red.add) ---
    init_feat_kernel<<<(NN * (DD / 4) + 255) / 256, 256>>>(feat);
    enc_gemm_kernel<<<dim3((NN + TBM - 1) / TBM, 2), 128, ENC_SMEM>>>(h, beff, feat);

    // ---- GraphConv 1: 64 -> 64, relu ----
    gemm64_kernel<<<gemm_grid(NN, DD, 1), 256>>>(feat, Wg0, xw, NN, DD, DD, cs, 1.0f, 0, 0, 0);
    gather64_kernel<<<(NN * 32 + 255) / 256, 256>>>(xw, y1, bg0);

    // ---- GraphConv 2: 64 -> 32, relu ----
    gemm64_kernel<<<gemm_grid(NN, 32, 1), 256>>>(y1, Wg1, xw, NN, DD, 32, cs, 1.0f, 0, 0, 0);
    gather32_kernel<<<(NN * 32 + 255) / 256, 256>>>(xw, y2, bg1);

    // ---- GraphConv 3: 32 -> 4, no relu, write output ----
    gemm64_kernel<<<gemm_grid(NN, 4, 1), 256>>>(y2, Wg2, xw, NN, 32, 4, cs, 1.0f, 0, 0, 0);
    gather4_kernel<<<(NN + 255) / 256, 256>>>(xw, out, bg2);
}

// round 14
// speedup vs baseline: 5.3200x; 1.0127x over previous
#include <cuda_runtime.h>
#include <cstdint>

#define NN   50000
#define NE   1600000
#define DIN  2000
#define H1   500
#define H2   128
#define DD   64
#define KTOT (2 * DIN)   // 4000

// A-operand tf32 truncation bias compensation (E[rel loss] for log-uniform mantissas;
// matches measured 7.055e-4 / 2 operands = 3.5275e-4)
#define BIAS_CORR 1.00035275f

// ---------------- scratch (static device globals; no allocation) ----------------
static __device__ float g_t2[2 * H1 * DD];      // diag(a1)W2 @ diag(a2)Wd
static __device__ float g_beff[KTOT * DD];      // [4000][64] effective weights (RNA tf32)
static __device__ float g_biasEff[DD];
static __device__ float g_feat[NN * DD];
static __device__ float g_xw[NN * DD];
static __device__ float g_y1[NN * DD];
static __device__ float g_y2[NN * 32];
static __device__ float g_cs[NN];
static __device__ float g_cd[NN];
static __device__ int   g_indeg[NN];
static __device__ int   g_offs[NN + 1];
static __device__ int   g_cursor[NN];
static __device__ int   g_ein[NE];              // edge src ids grouped by dst
static __device__ float g_alpha1[2 * H1], g_beta1[2 * H1];
static __device__ float g_alpha2[2 * H2], g_beta2[2 * H2];

// ---------------- helpers ----------------
__device__ __forceinline__ unsigned f2tf(float x)
{
    unsigned r;
    asm("cvt.rna.tf32.f32 %0, %1;" : "=r"(r) : "f"(x));
    return r;
}
__device__ __forceinline__ float f2tff(float x) { return __uint_as_float(f2tf(x)); }

__device__ __forceinline__ void mma_tf32(float* c, const unsigned* a, const unsigned* b)
{
    asm volatile(
        "mma.sync.aligned.m16n8k8.row.col.f32.tf32.tf32.f32 "
        "{%0,%1,%2,%3}, {%4,%5,%6,%7}, {%8,%9}, {%0,%1,%2,%3};\n"
        : "+f"(c[0]), "+f"(c[1]), "+f"(c[2]), "+f"(c[3])
        : "r"(a[0]), "r"(a[1]), "r"(a[2]), "r"(a[3]), "r"(b[0]), "r"(b[1]));
}

__device__ __forceinline__ void cp_async16z(uint32_t dst, const void* src, int sz)
{
    asm volatile("cp.async.cg.shared.global [%0], [%1], 16, %2;"
                 :: "r"(dst), "l"(src), "r"(sz));
}

// ---------------- prep: BN fold vectors ----------------
__global__ void prep_kernel(const float* __restrict__ b1, const float* __restrict__ g1,
                            const float* __restrict__ be1, const float* __restrict__ m1,
                            const float* __restrict__ v1,
                            const float* __restrict__ b2, const float* __restrict__ g2,
                            const float* __restrict__ be2, const float* __restrict__ m2,
                            const float* __restrict__ v2)
{
    int t = threadIdx.x;
    for (int i = t; i < 2 * H1; i += blockDim.x) {
        float a = g1[i] * rsqrtf(v1[i] + 1e-5f);
        g_alpha1[i] = a;
        g_beta1[i]  = (b1[i] - m1[i]) * a + be1[i];
    }
    for (int i = t; i < 2 * H2; i += blockDim.x) {
        float a = g2[i] * rsqrtf(v2[i] + 1e-5f);
        g_alpha2[i] = a;
        g_beta2[i]  = (b2[i] - m2[i]) * a + be2[i];
    }
}

__global__ void bias_chain_kernel(const float* __restrict__ W2, const float* __restrict__ b2,
                                  const float* __restrict__ Wd, const float* __restrict__ bd)
{
    __shared__ float v[2][H2];
    int t = threadIdx.x;   // 128 threads
    for (int m = 0; m < 2; m++) {
        float u = b2[m * H2 + t];
        for (int k = 0; k < H1; k++)
            u += g_beta1[m * H1 + k] * W2[(size_t)m * H1 * H2 + k * H2 + t];
        v[m][t] = u * g_alpha2[m * H2 + t] + g_beta2[m * H2 + t];
    }
    __syncthreads();
    if (t < DD) {
        float s = 0.f;
        for (int m = 0; m < 2; m++) {
            float tmp = bd[m * DD + t];
            for (int n = 0; n < H2; n++)
                tmp += v[m][n] * Wd[(size_t)m * H2 * DD + n * DD + t];
            s += 0.5f * tmp;
        }
        g_biasEff[t] = s;
    }
}

// RNA-round beff to tf32 (removes B-operand truncation bias)
__global__ void round_tf32_kernel(float* __restrict__ p, int n4)
{
    int i = blockIdx.x * blockDim.x + threadIdx.x;
    if (i < n4) {
        float4 v = ((float4*)p)[i];
        v.x = f2tff(v.x); v.y = f2tff(v.y); v.z = f2tff(v.z); v.w = f2tff(v.w);
        ((float4*)p)[i] = v;
    }
}

// feat[n][c] = biasEff[c]  (float4 granularity)
__global__ void init_feat_kernel(float* __restrict__ feat)
{
    int i = blockIdx.x * blockDim.x + threadIdx.x;
    if (i >= NN * (DD / 4)) return;
    int c4 = i & (DD / 4 - 1);
    ((float4*)feat)[i] = *(const float4*)(g_biasEff + c4 * 4);
}

// zero cs (float), indeg, cursor (int) in one pass
__global__ void zero_csr_kernel()
{
    int i = blockIdx.x * blockDim.x + threadIdx.x;
    if (i < NN) {
        g_cs[i] = 0.0f;
        g_indeg[i] = 0;
        g_cursor[i] = 0;
    }
}

// ---------------- degrees + CSR build ----------------
__global__ void deg_count_kernel(const int* __restrict__ src, const int* __restrict__ dst)
{
    int i = blockIdx.x * blockDim.x + threadIdx.x;
    if (i < NE) {
        atomicAdd(&g_cs[src[i]], 1.0f);
        atomicAdd(&g_indeg[dst[i]], 1);
    }
}

__global__ void deg_finish_kernel()
{
    int i = blockIdx.x * blockDim.x + threadIdx.x;
    if (i < NN) {
        g_cs[i] = rsqrtf(fmaxf(g_cs[i], 1.0f));
        g_cd[i] = rsqrtf(fmaxf((float)g_indeg[i], 1.0f));
    }
}

// single-block exclusive scan of indeg -> offs (shfl-based)
__global__ void scan_offsets_kernel()
{
    __shared__ int wsum[32];
    __shared__ int carryS;
    const int t = threadIdx.x;
    const int lane = t & 31;
    const int w = t >> 5;
    if (t == 0) carryS = 0;
    __syncthreads();
    for (int base = 0; base < NN; base += 1024) {
        int idx = base + t;
        int v = (idx < NN) ? g_indeg[idx] : 0;
        int s = v;
#pragma unroll
        for (int off = 1; off < 32; off <<= 1) {
            int x = __shfl_up_sync(0xffffffffu, s, off);
            if (lane >= off) s += x;
        }
        if (lane == 31) wsum[w] = s;
        __syncthreads();
        if (w == 0) {
            int ws = wsum[lane];
#pragma unroll
            for (int off = 1; off < 32; off <<= 1) {
                int x = __shfl_up_sync(0xffffffffu, ws, off);
                if (lane >= off) ws += x;
            }
            wsum[lane] = ws;
        }
        __syncthreads();
        int wpre = (w == 0) ? 0 : wsum[w - 1];
        int c = carryS;
        if (idx < NN) g_offs[idx] = c + wpre + s - v;
        __syncthreads();
        if (t == 0) carryS = c + wsum[31];
        __syncthreads();
    }
    if (threadIdx.x == 0) g_offs[NN] = carryS;
}

__global__ void bin_edges_kernel(const int* __restrict__ src, const int* __restrict__ dst)
{
    int e = blockIdx.x * blockDim.x + threadIdx.x;
    if (e < NE) {
        int d = dst[e];
        int p = g_offs[d] + atomicAdd(&g_cursor[d], 1);
        g_ein[p] = src[e];
    }
}

// ===== enc GEMM: split-K by modality, 4-stage cp.async, raw-fp32 tf32 (bias-compensated) =====
#define TBM 128
#define TBN 64
#define TBK 32
#define APW 36
#define BPW 72
#define STG_WORDS (TBM * APW + TBK * BPW)
#define ENC_SMEM (4 * STG_WORDS * 4)

__global__ __launch_bounds__(128, 2)
void enc_gemm_kernel(const float* __restrict__ h, const float* __restrict__ Beff,
                     float* __restrict__ C)
{
    extern __shared__ float smem[];

    const int t    = threadIdx.x;
    const int warp = t >> 5;
    const int lane = t & 31;
    const int bm   = blockIdx.x * TBM;
    const int m    = blockIdx.y;                 // modality split
    const int wm   = (warp >> 1) * 64;
    const int wn   = (warp & 1) * 32;

    const float* A = h + (size_t)m * NN * DIN;
    const float* B = Beff + (size_t)m * DIN * DD;

    const int aRow = t >> 3;             // 0..15, 8 passes of 16 rows
    const int aCol = (t & 7) * 4;        // 0..28
    const int bRow = t >> 4;             // 0..7, 4 passes of 8 k-rows
    const int bCol = (t & 15) * 4;       // 0..60

    const int nT = (DIN + TBK - 1) / TBK;        // 63 (last tile partial)

    auto issueAB = [&](int tt) {
        const int k0 = tt * TBK;
        float* As = smem + (tt & 3) * STG_WORDS;
        float* Bs = As + TBM * APW;
        const int kk = k0 + aCol;
        const int aok = (kk + 4 <= DIN);
#pragma unroll
        for (int i = 0; i < 8; i++) {
            int row = bm + aRow + i * 16;
            int sz = (aok && row < NN) ? 16 : 0;
            cp_async16z((uint32_t)__cvta_generic_to_shared(As + (aRow + i * 16) * APW + aCol),
                        A + (size_t)row * DIN + kk, sz);
        }
#pragma unroll
        for (int i = 0; i < 4; i++) {
            int k = bRow + i * 8;
            int sz = (k0 + k < DIN) ? 16 : 0;
            cp_async16z((uint32_t)__cvta_generic_to_shared(Bs + k * BPW + bCol),
                        B + (size_t)(k0 + k) * DD + bCol, sz);
        }
        asm volatile("cp.async.commit_group;");
    };

    float acc[4][4][4];
#pragma unroll
    for (int mi = 0; mi < 4; mi++)
#pragma unroll
        for (int ni = 0; ni < 4; ni++)
#pragma unroll
            for (int j = 0; j < 4; j++) acc[mi][ni][j] = 0.f;

    issueAB(0);
    issueAB(1);
    issueAB(2);

    for (int tt = 0; tt < nT; tt++) {
        if (tt + 3 < nT) {
            issueAB(tt + 3);
            asm volatile("cp.async.wait_group 3;");
        } else if (tt + 2 < nT) {
            asm volatile("cp.async.wait_group 2;");
        } else if (tt + 1 < nT) {
            asm volatile("cp.async.wait_group 1;");
        } else {
            asm volatile("cp.async.wait_group 0;");
        }
        __syncthreads();

        const float* As = smem + (tt & 3) * STG_WORDS;
        const float* Bs = As + TBM * APW;

#pragma unroll
        for (int ks = 0; ks < 4; ks++) {
            const int c = ks * 8 + (lane & 3);
            unsigned bf[4][2];
#pragma unroll
            for (int ni = 0; ni < 4; ni++) {
                int n = wn + ni * 8 + (lane >> 2);
                bf[ni][0] = __float_as_uint(Bs[c * BPW + n]);
                bf[ni][1] = __float_as_uint(Bs[(c + 4) * BPW + n]);
            }
#pragma unroll
            for (int mi = 0; mi < 4; mi++) {
                int r = wm + mi * 16 + (lane >> 2);
                unsigned af[4];
                af[0] = __float_as_uint(As[r * APW + c]);
                af[1] = __float_as_uint(As[(r + 8) * APW + c]);
                af[2] = __float_as_uint(As[r * APW + c + 4]);
                af[3] = __float_as_uint(As[(r + 8) * APW + c + 4]);
#pragma unroll
                for (int ni = 0; ni < 4; ni++)
                    mma_tf32(acc[mi][ni], af, bf[ni]);
            }
        }
        __syncthreads();
    }

    // epilogue: red.add partial into pre-initialized C
#pragma unroll
    for (int mi = 0; mi < 4; mi++) {
        int rbase = bm + wm + mi * 16 + (lane >> 2);
#pragma unroll
        for (int half = 0; half < 2; half++) {
            int row = rbase + half * 8;
            if (row >= NN) continue;
#pragma unroll
            for (int ni = 0; ni < 4; ni++) {
                int col = wn + ni * 8 + 2 * (lane & 3);
                float v0 = acc[mi][ni][half * 2];
                float v1 = acc[mi][ni][half * 2 + 1];
                float* p = C + (size_t)row * DD + col;
                asm volatile("red.global.add.v2.f32 [%0], {%1, %2};"
                             :: "l"(p), "f"(v0), "f"(v1) : "memory");
            }
        }
    }
}

// ---------------- SIMT 64x64 GEMM with batch z + optional A-row/B-row scales ----------------
__global__ __launch_bounds__(256)
void gemm64_kernel(const float* __restrict__ A, const float* __restrict__ B,
                   float* __restrict__ C, int M, int K, int Nc,
                   const float* __restrict__ rowScale, float scalarAlpha,
                   const float* __restrict__ bScale,
                   size_t aBStride, size_t bBStride, size_t cBStride,
                   size_t rsStride, size_t bsStride)
{
    __shared__ float As[16][64];
    __shared__ float Bs[16][64];

    const int z = blockIdx.z;
    const float* Az = A + z * aBStride;
    const float* Bz = B + z * bBStride;
    float*       Cz = C + z * cBStride;

    const int t  = threadIdx.x;
    const int bm = blockIdx.y * 64;
    const int bn = blockIdx.x * 64;

    const int a_row = t >> 2;
    const int a_col = (t & 3) * 4;
    const int b_row = t >> 4;
    const int b_col = (t & 15) * 4;

    const int tx = t & 15;
    const int ty = t >> 4;

    float acc[4][4];
#pragma unroll
    for (int i = 0; i < 4; i++)
#pragma unroll
        for (int j = 0; j < 4; j++) acc[i][j] = 0.0f;

    for (int k0 = 0; k0 < K; k0 += 16) {
        float4 av = make_float4(0.f, 0.f, 0.f, 0.f);
        int ar = bm + a_row;
        if (ar < M) {
            if (k0 + a_col + 3 < K) {
                av = *(const float4*)(Az + (size_t)ar * K + k0 + a_col);
            } else {
                float tmp[4] = {0.f, 0.f, 0.f, 0.f};
#pragma unroll
                for (int i = 0; i < 4; i++) {
                    int kk = k0 + a_col + i;
                    if (kk < K) tmp[i] = Az[(size_t)ar * K + kk];
                }
                av = make_float4(tmp[0], tmp[1], tmp[2], tmp[3]);
            }
        }
        As[a_col + 0][a_row] = av.x;
        As[a_col + 1][a_row] = av.y;
        As[a_col + 2][a_row] = av.z;
        As[a_col + 3][a_row] = av.w;

        float4 bv = make_float4(0.f, 0.f, 0.f, 0.f);
        int brr = k0 + b_row;
        int bcc = bn + b_col;
        if (brr < K) {
            if (bcc + 3 < Nc) {
                bv = *(const float4*)(Bz + (size_t)brr * Nc + bcc);
            } else {
                float tmp[4] = {0.f, 0.f, 0.f, 0.f};
#pragma unroll
                for (int i = 0; i < 4; i++) {
                    int cc = bcc + i;
                    if (cc < Nc) tmp[i] = Bz[(size_t)brr * Nc + cc];
                }
                bv = make_float4(tmp[0], tmp[1], tmp[2], tmp[3]);
            }
            if (bScale) {
                float s = bScale[z * bsStride + brr];
                bv.x *= s; bv.y *= s; bv.z *= s; bv.w *= s;
            }
        }
        *(float4*)&Bs[b_row][b_col] = bv;

        __syncthreads();

#pragma unroll
        for (int k = 0; k < 16; k++) {
            float4 a = *(const float4*)&As[k][ty * 4];
            float4 b = *(const float4*)&Bs[k][tx * 4];
            acc[0][0] += a.x * b.x; acc[0][1] += a.x * b.y; acc[0][2] += a.x * b.z; acc[0][3] += a.x * b.w;
            acc[1][0] += a.y * b.x; acc[1][1] += a.y * b.y; acc[1][2] += a.y * b.z; acc[1][3] += a.y * b.w;
            acc[2][0] += a.z * b.x; acc[2][1] += a.z * b.y; acc[2][2] += a.z * b.z; acc[2][3] += a.z * b.w;
            acc[3][0] += a.w * b.x; acc[3][1] += a.w * b.y; acc[3][2] += a.w * b.z; acc[3][3] += a.w * b.w;
        }
        __syncthreads();
    }

#pragma unroll
    for (int i = 0; i < 4; i++) {
        int row = bm + ty * 4 + i;
        if (row >= M) continue;
        float rs = rowScale ? rowScale[z * rsStride + row] : scalarAlpha;
#pragma unroll
        for (int j = 0; j < 4; j++) {
            int col = bn + tx * 4 + j;
            if (col >= Nc) continue;
            Cz[(size_t)row * Nc + col] = acc[i][j] * rs;
        }
    }
}

// ---------------- CSR gather-aggregate, fused cd*agg + bias (+relu), 4-way unroll ----------------
__global__ void gather64_kernel(const float* __restrict__ xw, float* __restrict__ out,
                                const float* __restrict__ bias)
{
    int node = blockIdx.x * (blockDim.x >> 5) + (threadIdx.x >> 5);
    if (node >= NN) return;
    int lane = threadIdx.x & 31;
    int beg = g_offs[node], end = g_offs[node + 1];
    float ax = 0.f, ay = 0.f;
    int e = beg;
    for (; e + 4 <= end; e += 4) {
        int s0 = g_ein[e], s1 = g_ein[e + 1], s2 = g_ein[e + 2], s3 = g_ein[e + 3];
        float2 v0 = *(const float2*)(xw + (size_t)s0 * 64 + lane * 2);
        float2 v1 = *(const float2*)(xw + (size_t)s1 * 64 + lane * 2);
        float2 v2 = *(const float2*)(xw + (size_t)s2 * 64 + lane * 2);
        float2 v3 = *(const float2*)(xw + (size_t)s3 * 64 + lane * 2);
        ax += (v0.x + v1.x) + (v2.x + v3.x);
        ay += (v0.y + v1.y) + (v2.y + v3.y);
    }
    for (; e < end; e++) {
        float2 v = *(const float2*)(xw + (size_t)g_ein[e] * 64 + lane * 2);
        ax += v.x; ay += v.y;
    }
    float cdv = g_cd[node];
    float o0 = fmaxf(ax * cdv + bias[lane * 2], 0.f);
    float o1 = fmaxf(ay * cdv + bias[lane * 2 + 1], 0.f);
    *(float2*)(out + (size_t)node * 64 + lane * 2) = make_float2(o0, o1);
}

__global__ void gather32_kernel(const float* __restrict__ xw, float* __restrict__ out,
                                const float* __restrict__ bias)
{
    int node = blockIdx.x * (blockDim.x >> 5) + (threadIdx.x >> 5);
    if (node >= NN) return;
    int lane = threadIdx.x & 31;
    int beg = g_offs[node], end = g_offs[node + 1];
    float a = 0.f;
    int e = beg;
    for (; e + 4 <= end; e += 4) {
        int s0 = g_ein[e], s1 = g_ein[e + 1], s2 = g_ein[e + 2], s3 = g_ein[e + 3];
        float v0 = xw[(size_t)s0 * 32 + lane];
        float v1 = xw[(size_t)s1 * 32 + lane];
        float v2 = xw[(size_t)s2 * 32 + lane];
        float v3 = xw[(size_t)s3 * 32 + lane];
        a += (v0 + v1) + (v2 + v3);
    }
    for (; e < end; e++)
        a += xw[(size_t)g_ein[e] * 32 + lane];
    out[(size_t)node * 32 + lane] = fmaxf(a * g_cd[node] + bias[lane], 0.f);
}

__global__ void gather4_kernel(const float* __restrict__ xw, float* __restrict__ out,
                               const float* __restrict__ bias)
{
    int node = blockIdx.x * blockDim.x + threadIdx.x;
    if (node >= NN) return;
    int beg = g_offs[node], end = g_offs[node + 1];
    float4 a = make_float4(0.f, 0.f, 0.f, 0.f);
    int e = beg;
    for (; e + 4 <= end; e += 4) {
        int s0 = g_ein[e], s1 = g_ein[e + 1], s2 = g_ein[e + 2], s3 = g_ein[e + 3];
        float4 v0 = *(const float4*)(xw + (size_t)s0 * 4);
        float4 v1 = *(const float4*)(xw + (size_t)s1 * 4);
        float4 v2 = *(const float4*)(xw + (size_t)s2 * 4);
        float4 v3 = *(const float4*)(xw + (size_t)s3 * 4);
        a.x += (v0.x + v1.x) + (v2.x + v3.x);
        a.y += (v0.y + v1.y) + (v2.y + v3.y);
        a.z += (v0.z + v1.z) + (v2.z + v3.z);
        a.w += (v0.w + v1.w) + (v2.w + v3.w);
    }
    for (; e < end; e++) {
        float4 v = *(const float4*)(xw + (size_t)g_ein[e] * 4);
        a.x += v.x; a.y += v.y; a.z += v.z; a.w += v.w;
    }
    float cdv = g_cd[node];
    a.x = a.x * cdv + bias[0];
    a.y = a.y * cdv + bias[1];
    a.z = a.z * cdv + bias[2];
    a.w = a.w * cdv + bias[3];
    *(float4*)(out + (size_t)node * 4) = a;
}

// ---------------- launch ----------------
static inline dim3 gemm_grid(int M, int Nc, int z)
{
    return dim3((Nc + 63) / 64, (M + 63) / 64, z);
}

extern "C" void kernel_launch(void* const* d_in, const int* in_sizes, int n_in,
                              void* d_out, int out_size)
{
    const float* h   = (const float*)d_in[0];
    const int*   src = (const int*)  d_in[1];
    const int*   dst = (const int*)  d_in[2];
    const float* W1  = (const float*)d_in[3];
    const float* b1  = (const float*)d_in[4];
    const float* g1  = (const float*)d_in[5];
    const float* be1 = (const float*)d_in[6];
    const float* m1  = (const float*)d_in[7];
    const float* v1  = (const float*)d_in[8];
    const float* W2  = (const float*)d_in[9];
    const float* b2  = (const float*)d_in[10];
    const float* g2  = (const float*)d_in[11];
    const float* be2 = (const float*)d_in[12];
    const float* m2  = (const float*)d_in[13];
    const float* v2  = (const float*)d_in[14];
    const float* Wd  = (const float*)d_in[15];
    const float* bd  = (const float*)d_in[16];
    const float* Wg0 = (const float*)d_in[17];
    const float* bg0 = (const float*)d_in[18];
    const float* Wg1 = (const float*)d_in[19];
    const float* bg1 = (const float*)d_in[20];
    const float* Wg2 = (const float*)d_in[21];
    const float* bg2 = (const float*)d_in[22];
    float* out = (float*)d_out;

    float *t2, *beff;
    float *feat, *xw, *y1, *y2, *cs, *alpha1, *alpha2;
    cudaGetSymbolAddress((void**)&t2, g_t2);
    cudaGetSymbolAddress((void**)&beff, g_beff);
    cudaGetSymbolAddress((void**)&feat, g_feat);
    cudaGetSymbolAddress((void**)&xw, g_xw);
    cudaGetSymbolAddress((void**)&y1, g_y1);
    cudaGetSymbolAddress((void**)&y2, g_y2);
    cudaGetSymbolAddress((void**)&cs, g_cs);
    cudaGetSymbolAddress((void**)&alpha1, g_alpha1);
    cudaGetSymbolAddress((void**)&alpha2, g_alpha2);

    cudaFuncSetAttribute(enc_gemm_kernel, cudaFuncAttributeMaxDynamicSharedMemorySize, ENC_SMEM);

    // --- fold the linear encoder into Beff [4000][64] + biasEff [64] ---
    prep_kernel<<<1, 512>>>(b1, g1, be1, m1, v1, b2, g2, be2, m2, v2);
    // t2_m = diag(a1_m) W2_m @ diag(a2_m) Wd_m  (scales fused into GEMM)
    gemm64_kernel<<<gemm_grid(H1, DD, 2), 256>>>(
        W2, Wd, t2, H1, H2, DD,
        alpha1, 1.0f, alpha2,
        (size_t)H1 * H2, (size_t)H2 * DD, (size_t)H1 * DD,
        (size_t)H1, (size_t)H2);
    // Beff_m = 0.5 * BIAS_CORR * W1_m @ t2_m  (truncation-bias compensation folded in)
    gemm64_kernel<<<gemm_grid(DIN, DD, 2), 256>>>(
        W1, t2, beff, DIN, H1, DD,
        nullptr, 0.5f * BIAS_CORR, nullptr,
        (size_t)DIN * H1, (size_t)H1 * DD, (size_t)DIN * DD, 0, 0);
    round_tf32_kernel<<<(KTOT * DD / 4 + 255) / 256, 256>>>(beff, KTOT * DD / 4);
    bias_chain_kernel<<<1, 128>>>(W2, b2, Wd, bd);

    // --- degrees + CSR ---
    zero_csr_kernel<<<(NN + 255) / 256, 256>>>();
    deg_count_kernel<<<(NE + 255) / 256, 256>>>(src, dst);
    deg_finish_kernel<<<(NN + 255) / 256, 256>>>();
    scan_offsets_kernel<<<1, 1024>>>();
    bin_edges_kernel<<<(NE + 255) / 256, 256>>>(src, dst);

    // --- collapsed encoder: feat = biasEff + sum_m h_m @ Beff_m (split-K, red.add) ---
    init_feat_kernel<<<(NN * (DD / 4) + 255) / 256, 256>>>(feat);
    enc_gemm_kernel<<<dim3((NN + TBM - 1) / TBM, 2), 128, ENC_SMEM>>>(h, beff, feat);

    // ---- GraphConv 1: 64 -> 64, relu ----
    gemm64_kernel<<<gemm_grid(NN, DD, 1), 256>>>(
        feat, Wg0, xw, NN, DD, DD, cs, 1.0f, nullptr, 0, 0, 0, 0, 0);
    gather64_kernel<<<(NN * 32 + 255) / 256, 256>>>(xw, y1, bg0);

    // ---- GraphConv 2: 64 -> 32, relu ----
    gemm64_kernel<<<gemm_grid(NN, 32, 1), 256>>>(
        y1, Wg1, xw, NN, DD, 32, cs, 1.0f, nullptr, 0, 0, 0, 0, 0);
    gather32_kernel<<<(NN * 32 + 255) / 256, 256>>>(xw, y2, bg1);

    // ---- GraphConv 3: 32 -> 4, no relu, write output ----
    gemm64_kernel<<<gemm_grid(NN, 4, 1), 256>>>(
        y2, Wg2, xw, NN, 32, 4, cs, 1.0f, nullptr, 0, 0, 0, 0, 0);
    gather4_kernel<<<(NN + 255) / 256, 256>>>(xw, out, bg2);
}